// round 10
// baseline (speedup 1.0000x reference)
#include <cuda_runtime.h>
#include <cuda_bf16.h>
#include <math.h>
#include <cstdint>

#define B      8192
#define IN_DIM 1024
#define HID    512
#define OUT    128

// scratch (device globals — no allocation allowed)
__device__ float g_h[B * HID];                                // 16 MB
__device__ __align__(256) __nv_bfloat16 g_x_hi[B * IN_DIM];   // 16 MB
__device__ __align__(256) __nv_bfloat16 g_x_lo[B * IN_DIM];   // 16 MB
__device__ __align__(256) __nv_bfloat16 g_w1t_hi[HID * IN_DIM]; // [n][k]
__device__ __align__(256) __nv_bfloat16 g_w1t_lo[HID * IN_DIM];
__device__ __align__(256) __nv_bfloat16 g_hn_hi[B * HID];     // 8 MB
__device__ __align__(256) __nv_bfloat16 g_hn_lo[B * HID];     // 8 MB
__device__ __align__(256) __nv_bfloat16 g_w2t_hi[OUT * HID];  // [n][k]
__device__ __align__(256) __nv_bfloat16 g_w2t_lo[OUT * HID];
__device__ __align__(256) __nv_bfloat16 g_zn_hi[B * OUT];     // 2 MB
__device__ __align__(256) __nv_bfloat16 g_zn_lo[B * OUT];     // 2 MB

__device__ __forceinline__ uint32_t smem_u32(const void* p) {
    uint32_t a;
    asm("{ .reg .u64 t; cvta.to.shared.u64 t, %1; cvt.u32.u64 %0, t; }"
        : "=r"(a) : "l"(p));
    return a;
}

#define LDSM_X4(r0, r1, r2, r3, addr) \
    asm volatile("ldmatrix.sync.aligned.m8n8.x4.shared.b16 {%0,%1,%2,%3}, [%4];" \
        : "=r"(r0), "=r"(r1), "=r"(r2), "=r"(r3) : "r"(addr))

#define MMA_BF16(d, a, b0, b1) \
    asm volatile("mma.sync.aligned.m16n8k16.row.col.f32.bf16.bf16.f32 " \
        "{%0,%1,%2,%3}, {%4,%5,%6,%7}, {%8,%9}, {%0,%1,%2,%3};" \
        : "+f"((d)[0]), "+f"((d)[1]), "+f"((d)[2]), "+f"((d)[3]) \
        : "r"((a)[0]), "r"((a)[1]), "r"((a)[2]), "r"((a)[3]), "r"(b0), "r"(b1))

#define CP16(dst, src) \
    asm volatile("cp.async.cg.shared.global [%0], [%1], 16;" \
        :: "r"(dst), "l"(src) : "memory")
#define CP_COMMIT() asm volatile("cp.async.commit_group;" ::: "memory")
#define CP_WAIT(n)  asm volatile("cp.async.wait_group %0;" :: "n"(n) : "memory")

// ---------------------------------------------------------------------------
// templated helpers
// ---------------------------------------------------------------------------
// 3-split HMMA over one K-chunk. Fragments (Ah, Al, Bh, Bl) loaded ONCE per
// k16-step and reused by all 3 split products: Ah*Bh + Ah*Bl + Al*Bh.
template<int RB, int NKS, int NM, int NJ>
__device__ __forceinline__ void mma3(uint32_t aH, uint32_t aL,
                                     uint32_t bH, uint32_t bL, float* acc)
{
#pragma unroll
    for (int ks = 0; ks < NKS; ++ks) {
        const uint32_t kb = (uint32_t)ks * 32;
        uint32_t ah[NM][4], al[NM][4];
#pragma unroll
        for (int i = 0; i < NM; ++i) {
            LDSM_X4(ah[i][0], ah[i][1], ah[i][2], ah[i][3],
                    aH + (uint32_t)i * 16 * RB + kb);
            LDSM_X4(al[i][0], al[i][1], al[i][2], al[i][3],
                    aL + (uint32_t)i * 16 * RB + kb);
        }
        uint32_t bh[NJ][2], bl[NJ][2];
#pragma unroll
        for (int p = 0; p < NJ / 2; ++p) {
            uint32_t r0, r1, r2, r3;
            LDSM_X4(r0, r1, r2, r3, bH + (uint32_t)p * 16 * RB + kb);
            bh[2 * p + 0][0] = r0; bh[2 * p + 0][1] = r2;
            bh[2 * p + 1][0] = r1; bh[2 * p + 1][1] = r3;
            LDSM_X4(r0, r1, r2, r3, bL + (uint32_t)p * 16 * RB + kb);
            bl[2 * p + 0][0] = r0; bl[2 * p + 0][1] = r2;
            bl[2 * p + 1][0] = r1; bl[2 * p + 1][1] = r3;
        }
#pragma unroll
        for (int i = 0; i < NM; ++i)
#pragma unroll
            for (int j = 0; j < NJ; ++j)
                MMA_BF16(&acc[(i * NJ + j) * 4], ah[i], bh[j][0], bh[j][1]);
#pragma unroll
        for (int i = 0; i < NM; ++i)
#pragma unroll
            for (int j = 0; j < NJ; ++j)
                MMA_BF16(&acc[(i * NJ + j) * 4], ah[i], bl[j][0], bl[j][1]);
#pragma unroll
        for (int i = 0; i < NM; ++i)
#pragma unroll
            for (int j = 0; j < NJ; ++j)
                MMA_BF16(&acc[(i * NJ + j) * 4], al[i], bh[j][0], bh[j][1]);
    }
}

// stage acc fragments into Cs (stride 133 floats)
template<int NM, int NJ>
__device__ __forceinline__ void stage_acc(
    float* Cs, const float* acc, int wm, int wn, int lane)
{
#pragma unroll
    for (int i = 0; i < NM; ++i) {
        const int r0 = wm * (NM * 16) + i * 16 + (lane >> 2);
#pragma unroll
        for (int j = 0; j < NJ; ++j) {
            const int c0 = wn * (NJ * 8) + j * 8 + (lane & 3) * 2;
            const float* f = &acc[(i * NJ + j) * 4];
            Cs[r0 * 133 + c0]           = f[0];
            Cs[r0 * 133 + c0 + 1]       = f[1];
            Cs[(r0 + 8) * 133 + c0]     = f[2];
            Cs[(r0 + 8) * 133 + c0 + 1] = f[3];
        }
    }
}

// cp.async ROWSx256B tile (RB=272)
template<int ROWS, int NTH>
__device__ __forceinline__ void cp_t256(
    const __nv_bfloat16* __restrict__ g, int gstride, uint32_t dst, int tid)
{
#pragma unroll
    for (int it = 0; it < ROWS * 16 / NTH; ++it) {
        const int idx = tid + it * NTH;
        const int row = idx >> 4, c16 = idx & 15;
        CP16(dst + row * 272 + c16 * 16, g + row * gstride + c16 * 8);
    }
}
// cp.async ROWSx128B tile (RB=144)
template<int ROWS, int NTH>
__device__ __forceinline__ void cp_t128(
    const __nv_bfloat16* __restrict__ g, int gstride, uint32_t dst, int tid)
{
#pragma unroll
    for (int it = 0; it < ROWS * 8 / NTH; ++it) {
        const int idx = tid + it * NTH;
        const int row = idx >> 3, c16 = idx & 7;
        CP16(dst + row * 144 + c16 * 16, g + row * gstride + c16 * 8);
    }
}

// ---------------------------------------------------------------------------
// Prologue kernels: split inputs to bf16 hi/lo (w transposed)
// ---------------------------------------------------------------------------
__global__ __launch_bounds__(256) void split_x_kernel(const float* __restrict__ x)
{
    const int idx = blockIdx.x * 256 + threadIdx.x;
    const float2 v = ((const float2*)x)[idx];
    const __nv_bfloat16 h0 = __float2bfloat16(v.x);
    const __nv_bfloat16 h1 = __float2bfloat16(v.y);
    g_x_hi[2 * idx]     = h0;
    g_x_hi[2 * idx + 1] = h1;
    g_x_lo[2 * idx]     = __float2bfloat16(v.x - __bfloat162float(h0));
    g_x_lo[2 * idx + 1] = __float2bfloat16(v.y - __bfloat162float(h1));
}

__global__ __launch_bounds__(256) void split_w1t_kernel(const float* __restrict__ w1)
{
    const int idx = blockIdx.x * 256 + threadIdx.x;
    const int n = idx >> 10, k = idx & 1023;
    const float v = w1[k * HID + n];
    const __nv_bfloat16 h = __float2bfloat16(v);
    g_w1t_hi[idx] = h;
    g_w1t_lo[idx] = __float2bfloat16(v - __bfloat162float(h));
}

__global__ __launch_bounds__(256) void split_w2t_kernel(const float* __restrict__ w2)
{
    const int idx = blockIdx.x * 256 + threadIdx.x;
    const int n = idx >> 9, k = idx & 511;
    const float v = w2[k * OUT + n];
    const __nv_bfloat16 h = __float2bfloat16(v);
    g_w2t_hi[idx] = h;
    g_w2t_lo[idx] = __float2bfloat16(v - __bfloat162float(h));
}

// ---------------------------------------------------------------------------
// Kernel 1: h = PReLU(x @ w1 + b1). tile 128x64, BK=64, 2-stage cp.async,
// 256 threads (8 warps 4x2, warp tile 32x32), 2 CTAs/SM.
// ---------------------------------------------------------------------------
#define G1_TA    (128 * 144)          // 18432
#define G1_TB    (64 * 144)           // 9216
#define G1_STAGE (2 * G1_TA + 2 * G1_TB)  // 55296: [Ah, Al, Bh, Bl]
#define G1_SMEM  (2 * G1_STAGE)       // 110592 (<= 113 KB -> 2 CTAs/SM)

__global__ __launch_bounds__(256, 2) void gemm1_mma_kernel(
    const float* __restrict__ b1, const float* __restrict__ prelu_a)
{
    extern __shared__ char smem[];
    const uint32_t sb = smem_u32(smem);
    const int tid = threadIdx.x;
    const int wid = tid >> 5;
    const int lane = tid & 31;
    const int wm = wid & 3, wn = wid >> 2;   // 4x2 warps, warp tile 32x32
    const int rb = blockIdx.y, cb = blockIdx.x;

    const __nv_bfloat16* xh = g_x_hi   + (size_t)(rb * 128) * IN_DIM;
    const __nv_bfloat16* xl = g_x_lo   + (size_t)(rb * 128) * IN_DIM;
    const __nv_bfloat16* wh = g_w1t_hi + (size_t)(cb * 64) * IN_DIM;
    const __nv_bfloat16* wl = g_w1t_lo + (size_t)(cb * 64) * IN_DIM;

    cp_t128<128, 256>(xh, IN_DIM, sb + 0,                 tid);
    cp_t128<128, 256>(xl, IN_DIM, sb + G1_TA,             tid);
    cp_t128<64, 256> (wh, IN_DIM, sb + 2 * G1_TA,         tid);
    cp_t128<64, 256> (wl, IN_DIM, sb + 2 * G1_TA + G1_TB, tid);
    CP_COMMIT();

    const uint32_t lrow = (uint32_t)(lane & 15);
    const uint32_t lcol = (uint32_t)(lane >> 4) * 16;
    const uint32_t aoff = (uint32_t)(wm * 32) * 144 + lrow * 144 + lcol;
    const uint32_t boff = (uint32_t)(wn * 32) * 144 + lrow * 144 + lcol;

    float acc[2 * 4 * 4] = {};

    for (int kt = 0; kt < 16; ++kt) {
        if (kt < 15) {
            const int k0 = (kt + 1) * 64;
            const uint32_t st = sb + ((kt + 1) & 1) * G1_STAGE;
            cp_t128<128, 256>(xh + k0, IN_DIM, st + 0,                 tid);
            cp_t128<128, 256>(xl + k0, IN_DIM, st + G1_TA,             tid);
            cp_t128<64, 256> (wh + k0, IN_DIM, st + 2 * G1_TA,         tid);
            cp_t128<64, 256> (wl + k0, IN_DIM, st + 2 * G1_TA + G1_TB, tid);
            CP_COMMIT();
            CP_WAIT(1);
        } else {
            CP_WAIT(0);
        }
        __syncthreads();
        const uint32_t st = sb + (kt & 1) * G1_STAGE;
        mma3<144, 4, 2, 4>(st + aoff, st + G1_TA + aoff,
                           st + 2 * G1_TA + boff, st + 2 * G1_TA + G1_TB + boff,
                           acc);
        __syncthreads();
    }

    float* Cs = (float*)smem;   // 128 x 133 floats = 68096 B
    stage_acc<2, 4>(Cs, acc, wm, wn, lane);
    __syncthreads();

    const float alpha = prelu_a[0];
#pragma unroll
    for (int it = 0; it < 32; ++it) {
        const int idx = tid + it * 256;
        const int r = idx >> 6, c = idx & 63;
        float v = Cs[r * 133 + c] + b1[cb * 64 + c];
        v = (v >= 0.0f) ? v : alpha * v;
        g_h[(size_t)(rb * 128 + r) * HID + cb * 64 + c] = v;
    }
}

// ---------------------------------------------------------------------------
// Kernel 2: LayerNorm rows of g_h -> hn split bf16 hi/lo
// ---------------------------------------------------------------------------
__global__ __launch_bounds__(128) void ln_split_kernel(
    const float* __restrict__ gamma, const float* __restrict__ beta)
{
    const int row = blockIdx.x;
    const float* hp = g_h + row * HID;
    const int tid = threadIdx.x;

    float v[4];
    float s = 0.f, ss = 0.f;
#pragma unroll
    for (int i = 0; i < 4; ++i) {
        v[i] = hp[tid + i * 128];
        s  += v[i];
        ss += v[i] * v[i];
    }
#pragma unroll
    for (int o = 16; o > 0; o >>= 1) {
        s  += __shfl_xor_sync(0xFFFFFFFFu, s,  o);
        ss += __shfl_xor_sync(0xFFFFFFFFu, ss, o);
    }
    __shared__ float sm[4], sm2[4];
    if ((tid & 31) == 0) { sm[tid >> 5] = s; sm2[tid >> 5] = ss; }
    __syncthreads();
    s  = sm[0]  + sm[1]  + sm[2]  + sm[3];
    ss = sm2[0] + sm2[1] + sm2[2] + sm2[3];

    const float mu   = s * (1.0f / HID);
    const float var  = ss * (1.0f / HID) - mu * mu;
    const float rstd = rsqrtf(var + 1e-6f);
#pragma unroll
    for (int i = 0; i < 4; ++i) {
        const int c = tid + i * 128;
        const float hn = (v[i] - mu) * rstd * gamma[c] + beta[c];
        const __nv_bfloat16 hi = __float2bfloat16(hn);
        g_hn_hi[row * HID + c] = hi;
        g_hn_lo[row * HID + c] = __float2bfloat16(hn - __bfloat162float(hi));
    }
}

// ---------------------------------------------------------------------------
// Kernel 3: z = hn @ w2 + b2; epilogue row-norm + zn split.
// tile 64x128, BK=128, 2-stage cp.async. 256 threads. grid = 128 CTAs.
// ---------------------------------------------------------------------------
#define G2_TA    (64 * 272)            // 17408
#define G2_TB    (128 * 272)           // 34816
#define G2_STAGE (2 * G2_TA + 2 * G2_TB)  // 104448
#define G2_SMEM  (2 * G2_STAGE)        // 208896

__global__ __launch_bounds__(256, 1) void gemm2_mma_kernel(
    const float* __restrict__ b2, float* __restrict__ z_out)
{
    extern __shared__ char smem[];
    const uint32_t sb = smem_u32(smem);
    const int tid = threadIdx.x;
    const int wid = tid >> 5;
    const int lane = tid & 31;
    const int wm = wid & 1, wn = wid >> 1;   // 2x4 warps, warp tile 32x32
    const int rb = blockIdx.x;

    const __nv_bfloat16* ah = g_hn_hi + (size_t)(rb * 64) * HID;
    const __nv_bfloat16* al = g_hn_lo + (size_t)(rb * 64) * HID;

    cp_t256<64, 256> (ah,       HID, sb + 0,                 tid);
    cp_t256<64, 256> (al,       HID, sb + G2_TA,             tid);
    cp_t256<128, 256>(g_w2t_hi, HID, sb + 2 * G2_TA,         tid);
    cp_t256<128, 256>(g_w2t_lo, HID, sb + 2 * G2_TA + G2_TB, tid);
    CP_COMMIT();

    const uint32_t lrow = (uint32_t)(lane & 15);
    const uint32_t lcol = (uint32_t)(lane >> 4) * 16;
    const uint32_t aoff = (uint32_t)(wm * 32) * 272 + lrow * 272 + lcol;
    const uint32_t boff = (uint32_t)(wn * 32) * 272 + lrow * 272 + lcol;

    float acc[2 * 4 * 4] = {};

    for (int kt = 0; kt < 4; ++kt) {
        if (kt < 3) {
            const int k0 = (kt + 1) * 128;
            const uint32_t st = sb + ((kt + 1) & 1) * G2_STAGE;
            cp_t256<64, 256> (ah + k0,       HID, st + 0,                 tid);
            cp_t256<64, 256> (al + k0,       HID, st + G2_TA,             tid);
            cp_t256<128, 256>(g_w2t_hi + k0, HID, st + 2 * G2_TA,         tid);
            cp_t256<128, 256>(g_w2t_lo + k0, HID, st + 2 * G2_TA + G2_TB, tid);
            CP_COMMIT();
            CP_WAIT(1);
        } else {
            CP_WAIT(0);
        }
        __syncthreads();
        const uint32_t st = sb + (kt & 1) * G2_STAGE;
        mma3<272, 8, 2, 4>(st + aoff, st + G2_TA + aoff,
                           st + 2 * G2_TA + boff, st + 2 * G2_TA + G2_TB + boff,
                           acc);
        __syncthreads();
    }

    float* Cs = (float*)smem;
    stage_acc<2, 4>(Cs, acc, wm, wn, lane);
    __syncthreads();

    if (tid < 64) {
        const int r = tid;
        const int grow = rb * 64 + r;
        float s = 0.f;
#pragma unroll 8
        for (int c = 0; c < 128; ++c) {
            const float v = Cs[r * 133 + c] + b2[c];
            Cs[r * 133 + c] = v;
            s += v * v;
        }
        const float inv = 1.0f / fmaxf(sqrtf(s), 1e-8f);
#pragma unroll 8
        for (int c = 0; c < 128; ++c) {
            const float v = Cs[r * 133 + c];
            z_out[grow * OUT + c] = v;
            const float zn = v * inv;
            const __nv_bfloat16 hi = __float2bfloat16(zn);
            g_zn_hi[grow * OUT + c] = hi;
            g_zn_lo[grow * OUT + c] = __float2bfloat16(zn - __bfloat162float(hi));
        }
    }
}

// ---------------------------------------------------------------------------
// Kernel 4: y_hat = zn @ zn^T. 256 threads (8 warps 4x2, warp tile 32x64).
// Each CTA: one bi row-band, up to 4 j-tiles; A resident, B double-buffered.
// ---------------------------------------------------------------------------
#define GR_TILE  (128 * 272)           // 34816
#define GR_A     (2 * GR_TILE)         // 69632
#define GR_STAGE (2 * GR_TILE)         // 69632
#define GR_SMEM  (GR_A + 2 * GR_STAGE) // 208896
#define NT       (B / 128)             // 64
#define JPC      4

__global__ __launch_bounds__(256, 1) void gram_mma_kernel(float* __restrict__ yhat)
{
    int t = blockIdx.x;
    int bi = 0;
    for (; bi < NT; ++bi) {
        const int c = (NT - bi + JPC - 1) >> 2;
        if (t < c) break;
        t -= c;
    }
    const int j0 = bi + t * JPC;
    const int count = min(JPC, NT - j0);

    extern __shared__ char smem[];
    const uint32_t sb = smem_u32(smem);
    const int tid = threadIdx.x;
    const int wid = tid >> 5;
    const int lane = tid & 31;
    const int wm = wid & 3, wn = wid >> 2;

    cp_t256<128, 256>(g_zn_hi + (size_t)(bi * 128) * OUT, OUT, sb + 0 * GR_TILE, tid);
    cp_t256<128, 256>(g_zn_lo + (size_t)(bi * 128) * OUT, OUT, sb + 1 * GR_TILE, tid);
    cp_t256<128, 256>(g_zn_hi + (size_t)(j0 * 128) * OUT, OUT, sb + GR_A + 0 * GR_TILE, tid);
    cp_t256<128, 256>(g_zn_lo + (size_t)(j0 * 128) * OUT, OUT, sb + GR_A + 1 * GR_TILE, tid);
    CP_COMMIT();
    if (count > 1) {
        cp_t256<128, 256>(g_zn_hi + (size_t)((j0 + 1) * 128) * OUT, OUT,
                          sb + GR_A + GR_STAGE + 0 * GR_TILE, tid);
        cp_t256<128, 256>(g_zn_lo + (size_t)((j0 + 1) * 128) * OUT, OUT,
                          sb + GR_A + GR_STAGE + 1 * GR_TILE, tid);
        CP_COMMIT();
    }

    const uint32_t lrow = (uint32_t)(lane & 15);
    const uint32_t lcol = (uint32_t)(lane >> 4) * 16;
    const uint32_t aoff = (uint32_t)(wm * 32) * 272 + lrow * 272 + lcol;
    const uint32_t boff = (uint32_t)(wn * 64) * 272 + lrow * 272 + lcol;

    for (int jj = 0; jj < count; ++jj) {
        const int p = jj & 1;
        const int bj = j0 + jj;
        const uint32_t bst = sb + GR_A + p * GR_STAGE;

        if (jj + 1 < count) { CP_WAIT(1); } else { CP_WAIT(0); }
        __syncthreads();

        float acc[2 * 8 * 4] = {};
        mma3<272, 8, 2, 8>(sb + aoff, sb + GR_TILE + aoff,
                           bst + boff, bst + GR_TILE + boff, acc);
        __syncthreads();

        float* Cs = (float*)(smem + GR_A + p * GR_STAGE);  // consumed B stage
        stage_acc<2, 8>(Cs, acc, wm, wn, lane);
        __syncthreads();

        const long rowD = (long)bi * 128;
        const long colD = (long)bj * 128;
#pragma unroll
        for (int it = 0; it < 64; ++it) {
            const int idx = tid + it * 256;
            const int r = idx >> 7, c = idx & 127;
            yhat[(rowD + r) * (long)B + colD + c] = Cs[r * 133 + c];
        }
        if (bi != bj) {
#pragma unroll
            for (int it = 0; it < 64; ++it) {
                const int idx = tid + it * 256;
                const int r = idx >> 7, c = idx & 127;
                yhat[(colD + r) * (long)B + rowD + c] = Cs[c * 133 + r];
            }
        }
        __syncthreads();

        if (jj + 2 < count) {
            cp_t256<128, 256>(g_zn_hi + ((long)(j0 + jj + 2) * 128) * OUT, OUT,
                              sb + GR_A + p * GR_STAGE + 0 * GR_TILE, tid);
            cp_t256<128, 256>(g_zn_lo + ((long)(j0 + jj + 2) * 128) * OUT, OUT,
                              sb + GR_A + p * GR_STAGE + 1 * GR_TILE, tid);
            CP_COMMIT();
        }
    }
}

#define GRAM_GRID 544   // sum over bi of ceil((NT-bi)/JPC)

// ---------------------------------------------------------------------------
extern "C" void kernel_launch(void* const* d_in, const int* in_sizes, int n_in,
                              void* d_out, int out_size)
{
    const float* x       = (const float*)d_in[0];
    const float* w1      = (const float*)d_in[1];
    const float* b1      = (const float*)d_in[2];
    const float* prelu_a = (const float*)d_in[3];
    const float* gamma   = (const float*)d_in[4];
    const float* beta    = (const float*)d_in[5];
    const float* w2      = (const float*)d_in[6];
    const float* b2      = (const float*)d_in[7];

    float* out   = (float*)d_out;
    float* z_out = out;                    // [8192, 128]
    float* yhat  = out + (size_t)B * OUT;  // [8192, 8192]

    cudaFuncSetAttribute(gemm1_mma_kernel, cudaFuncAttributeMaxDynamicSharedMemorySize, G1_SMEM);
    cudaFuncSetAttribute(gemm2_mma_kernel, cudaFuncAttributeMaxDynamicSharedMemorySize, G2_SMEM);
    cudaFuncSetAttribute(gram_mma_kernel,  cudaFuncAttributeMaxDynamicSharedMemorySize, GR_SMEM);

    split_x_kernel<<<(B * IN_DIM / 2) / 256, 256>>>(x);
    split_w1t_kernel<<<(HID * IN_DIM) / 256, 256>>>(w1);
    split_w2t_kernel<<<(OUT * HID) / 256, 256>>>(w2);

    gemm1_mma_kernel<<<dim3(HID / 64, B / 128), 256, G1_SMEM>>>(b1, prelu_a);
    ln_split_kernel<<<B, 128>>>(gamma, beta);
    gemm2_mma_kernel<<<B / 64, 256, G2_SMEM>>>(b2, z_out);
    gram_mma_kernel<<<GRAM_GRID, 256, GR_SMEM>>>(yhat);
}

// round 11
// speedup vs baseline: 1.2494x; 1.2494x over previous
#include <cuda_runtime.h>
#include <cuda_fp16.h>
#include <math.h>
#include <cstdint>

#define B      8192
#define IN_DIM 1024
#define HID    512
#define OUT    128

// scratch (device globals — no allocation allowed)
__device__ float g_h[B * HID];                               // 16 MB
__device__ __align__(256) __half g_x_h[B * IN_DIM];          // 16 MB (fp16 quantized x)
__device__ __align__(256) __half g_w1t_h[HID * IN_DIM];      // [n][k] hi
__device__ __align__(256) __half g_w1t_l[HID * IN_DIM];      // [n][k] lo
__device__ __align__(256) __half g_hn_h[B * HID];            // 8 MB (fp16 quantized hn)
__device__ __align__(256) __half g_w2t_h[OUT * HID];         // [n][k] hi
__device__ __align__(256) __half g_w2t_l[OUT * HID];         // [n][k] lo
__device__ __align__(256) __half g_zn_h[B * OUT];            // 2 MB hi
__device__ __align__(256) __half g_zn_l[B * OUT];            // 2 MB lo

__device__ __forceinline__ uint32_t smem_u32(const void* p) {
    uint32_t a;
    asm("{ .reg .u64 t; cvta.to.shared.u64 t, %1; cvt.u32.u64 %0, t; }"
        : "=r"(a) : "l"(p));
    return a;
}

#define LDSM_X4(r0, r1, r2, r3, addr) \
    asm volatile("ldmatrix.sync.aligned.m8n8.x4.shared.b16 {%0,%1,%2,%3}, [%4];" \
        : "=r"(r0), "=r"(r1), "=r"(r2), "=r"(r3) : "r"(addr))

#define MMA_F16(d, a, b0, b1) \
    asm volatile("mma.sync.aligned.m16n8k16.row.col.f32.f16.f16.f32 " \
        "{%0,%1,%2,%3}, {%4,%5,%6,%7}, {%8,%9}, {%0,%1,%2,%3};" \
        : "+f"((d)[0]), "+f"((d)[1]), "+f"((d)[2]), "+f"((d)[3]) \
        : "r"((a)[0]), "r"((a)[1]), "r"((a)[2]), "r"((a)[3]), "r"(b0), "r"(b1))

#define CP16(dst, src) \
    asm volatile("cp.async.cg.shared.global [%0], [%1], 16;" \
        :: "r"(dst), "l"(src) : "memory")
#define CP_COMMIT() asm volatile("cp.async.commit_group;" ::: "memory")
#define CP_WAIT(n)  asm volatile("cp.async.wait_group %0;" :: "n"(n) : "memory")

// ---------------------------------------------------------------------------
// templated helpers
// ---------------------------------------------------------------------------
// 2-product HMMA over one K-chunk: A_q * (B_hi + B_lo). Fragments loaded once
// per k16-step. RB = smem row stride bytes, NKS = k16 steps, NM/NJ = frags.
template<int RB, int NKS, int NM, int NJ>
__device__ __forceinline__ void mma2(uint32_t aQ, uint32_t bH, uint32_t bL,
                                     float* acc)
{
#pragma unroll
    for (int ks = 0; ks < NKS; ++ks) {
        const uint32_t kb = (uint32_t)ks * 32;
        uint32_t a[NM][4];
#pragma unroll
        for (int i = 0; i < NM; ++i)
            LDSM_X4(a[i][0], a[i][1], a[i][2], a[i][3],
                    aQ + (uint32_t)i * 16 * RB + kb);
        uint32_t bh[NJ][2], bl[NJ][2];
#pragma unroll
        for (int p = 0; p < NJ / 2; ++p) {
            uint32_t r0, r1, r2, r3;
            LDSM_X4(r0, r1, r2, r3, bH + (uint32_t)p * 16 * RB + kb);
            bh[2 * p + 0][0] = r0; bh[2 * p + 0][1] = r2;
            bh[2 * p + 1][0] = r1; bh[2 * p + 1][1] = r3;
            LDSM_X4(r0, r1, r2, r3, bL + (uint32_t)p * 16 * RB + kb);
            bl[2 * p + 0][0] = r0; bl[2 * p + 0][1] = r2;
            bl[2 * p + 1][0] = r1; bl[2 * p + 1][1] = r3;
        }
#pragma unroll
        for (int i = 0; i < NM; ++i)
#pragma unroll
            for (int j = 0; j < NJ; ++j)
                MMA_F16(&acc[(i * NJ + j) * 4], a[i], bh[j][0], bh[j][1]);
#pragma unroll
        for (int i = 0; i < NM; ++i)
#pragma unroll
            for (int j = 0; j < NJ; ++j)
                MMA_F16(&acc[(i * NJ + j) * 4], a[i], bl[j][0], bl[j][1]);
    }
}

// stage acc fragments into Cs (stride 133 floats)
template<int NM, int NJ>
__device__ __forceinline__ void stage_acc(
    float* Cs, const float* acc, int wm, int wn, int lane)
{
#pragma unroll
    for (int i = 0; i < NM; ++i) {
        const int r0 = wm * (NM * 16) + i * 16 + (lane >> 2);
#pragma unroll
        for (int j = 0; j < NJ; ++j) {
            const int c0 = wn * (NJ * 8) + j * 8 + (lane & 3) * 2;
            const float* f = &acc[(i * NJ + j) * 4];
            Cs[r0 * 133 + c0]           = f[0];
            Cs[r0 * 133 + c0 + 1]       = f[1];
            Cs[(r0 + 8) * 133 + c0]     = f[2];
            Cs[(r0 + 8) * 133 + c0 + 1] = f[3];
        }
    }
}

// cp.async ROWSx256B tile (RB=272)
template<int ROWS, int NTH>
__device__ __forceinline__ void cp_t256(
    const __half* __restrict__ g, int gstride, uint32_t dst, int tid)
{
#pragma unroll
    for (int it = 0; it < ROWS * 16 / NTH; ++it) {
        const int idx = tid + it * NTH;
        const int row = idx >> 4, c16 = idx & 15;
        CP16(dst + row * 272 + c16 * 16, g + row * gstride + c16 * 8);
    }
}
// cp.async ROWSx128B tile (RB=144)
template<int ROWS, int NTH>
__device__ __forceinline__ void cp_t128(
    const __half* __restrict__ g, int gstride, uint32_t dst, int tid)
{
#pragma unroll
    for (int it = 0; it < ROWS * 8 / NTH; ++it) {
        const int idx = tid + it * NTH;
        const int row = idx >> 3, c16 = idx & 7;
        CP16(dst + row * 144 + c16 * 16, g + row * gstride + c16 * 8);
    }
}

// ---------------------------------------------------------------------------
// Prologue kernels: quantize/split inputs to fp16 (weights transposed+split)
// ---------------------------------------------------------------------------
__global__ __launch_bounds__(256) void split_x_kernel(const float* __restrict__ x)
{
    const int idx = blockIdx.x * 256 + threadIdx.x;
    const float2 v = ((const float2*)x)[idx];
    g_x_h[2 * idx]     = __float2half(v.x);
    g_x_h[2 * idx + 1] = __float2half(v.y);
}

__global__ __launch_bounds__(256) void split_w1t_kernel(const float* __restrict__ w1)
{
    const int idx = blockIdx.x * 256 + threadIdx.x;
    const int n = idx >> 10, k = idx & 1023;
    const float v = w1[k * HID + n];
    const __half h = __float2half(v);
    g_w1t_h[idx] = h;
    g_w1t_l[idx] = __float2half(v - __half2float(h));
}

__global__ __launch_bounds__(256) void split_w2t_kernel(const float* __restrict__ w2)
{
    const int idx = blockIdx.x * 256 + threadIdx.x;
    const int n = idx >> 9, k = idx & 511;
    const float v = w2[k * OUT + n];
    const __half h = __float2half(v);
    g_w2t_h[idx] = h;
    g_w2t_l[idx] = __float2half(v - __half2float(h));
}

// ---------------------------------------------------------------------------
// Kernel 1: h = PReLU(x @ w1 + b1). tile 128x128, BK=64, 2-stage cp.async,
// 256 threads (8 warps 4x2, warp tile 32x64). Stage: [Aq, Bh, Bl].
// ---------------------------------------------------------------------------
#define G1_T     (128 * 144)          // 18432
#define G1_STAGE (3 * G1_T)           // 55296
#define G1_SMEM  (2 * G1_STAGE)       // 110592

__global__ __launch_bounds__(256, 1) void gemm1_mma_kernel(
    const float* __restrict__ b1, const float* __restrict__ prelu_a)
{
    extern __shared__ char smem[];
    const uint32_t sb = smem_u32(smem);
    const int tid = threadIdx.x;
    const int wid = tid >> 5;
    const int lane = tid & 31;
    const int wm = wid & 3, wn = wid >> 2;
    const int rb = blockIdx.y, cb = blockIdx.x;

    const __half* xq = g_x_h   + (size_t)(rb * 128) * IN_DIM;
    const __half* wh = g_w1t_h + (size_t)(cb * 128) * IN_DIM;
    const __half* wl = g_w1t_l + (size_t)(cb * 128) * IN_DIM;

    cp_t128<128, 256>(xq, IN_DIM, sb + 0 * G1_T, tid);
    cp_t128<128, 256>(wh, IN_DIM, sb + 1 * G1_T, tid);
    cp_t128<128, 256>(wl, IN_DIM, sb + 2 * G1_T, tid);
    CP_COMMIT();

    const uint32_t lrow = (uint32_t)(lane & 15);
    const uint32_t lcol = (uint32_t)(lane >> 4) * 16;
    const uint32_t aoff = (uint32_t)(wm * 32) * 144 + lrow * 144 + lcol;
    const uint32_t boff = (uint32_t)(wn * 64) * 144 + lrow * 144 + lcol;

    float acc[2 * 8 * 4] = {};

    for (int kt = 0; kt < 16; ++kt) {
        if (kt < 15) {
            const int k0 = (kt + 1) * 64;
            const uint32_t st = sb + ((kt + 1) & 1) * G1_STAGE;
            cp_t128<128, 256>(xq + k0, IN_DIM, st + 0 * G1_T, tid);
            cp_t128<128, 256>(wh + k0, IN_DIM, st + 1 * G1_T, tid);
            cp_t128<128, 256>(wl + k0, IN_DIM, st + 2 * G1_T, tid);
            CP_COMMIT();
            CP_WAIT(1);
        } else {
            CP_WAIT(0);
        }
        __syncthreads();
        const uint32_t st = sb + (kt & 1) * G1_STAGE;
        mma2<144, 4, 2, 8>(st + aoff, st + G1_T + boff, st + 2 * G1_T + boff,
                           acc);
        __syncthreads();
    }

    float* Cs = (float*)smem;   // 128 x 133 floats = 68096 B
    stage_acc<2, 8>(Cs, acc, wm, wn, lane);
    __syncthreads();

    const float alpha = prelu_a[0];
#pragma unroll
    for (int it = 0; it < 64; ++it) {
        const int idx = tid + it * 256;
        const int r = idx >> 7, c = idx & 127;
        float v = Cs[r * 133 + c] + b1[cb * 128 + c];
        v = (v >= 0.0f) ? v : alpha * v;
        g_h[(size_t)(rb * 128 + r) * HID + cb * 128 + c] = v;
    }
}

// ---------------------------------------------------------------------------
// Kernel 2: LayerNorm rows of g_h -> hn quantized fp16
// ---------------------------------------------------------------------------
__global__ __launch_bounds__(128) void ln_split_kernel(
    const float* __restrict__ gamma, const float* __restrict__ beta)
{
    const int row = blockIdx.x;
    const float* hp = g_h + row * HID;
    const int tid = threadIdx.x;

    float v[4];
    float s = 0.f, ss = 0.f;
#pragma unroll
    for (int i = 0; i < 4; ++i) {
        v[i] = hp[tid + i * 128];
        s  += v[i];
        ss += v[i] * v[i];
    }
#pragma unroll
    for (int o = 16; o > 0; o >>= 1) {
        s  += __shfl_xor_sync(0xFFFFFFFFu, s,  o);
        ss += __shfl_xor_sync(0xFFFFFFFFu, ss, o);
    }
    __shared__ float sm[4], sm2[4];
    if ((tid & 31) == 0) { sm[tid >> 5] = s; sm2[tid >> 5] = ss; }
    __syncthreads();
    s  = sm[0]  + sm[1]  + sm[2]  + sm[3];
    ss = sm2[0] + sm2[1] + sm2[2] + sm2[3];

    const float mu   = s * (1.0f / HID);
    const float var  = ss * (1.0f / HID) - mu * mu;
    const float rstd = rsqrtf(var + 1e-6f);
#pragma unroll
    for (int i = 0; i < 4; ++i) {
        const int c = tid + i * 128;
        const float hn = (v[i] - mu) * rstd * gamma[c] + beta[c];
        g_hn_h[row * HID + c] = __float2half(hn);
    }
}

// ---------------------------------------------------------------------------
// Kernel 3: z = hn_q @ w2 + b2; epilogue row-norm + zn hi/lo split.
// tile 64x128, BK=128, 2-stage cp.async. 256 threads. grid = 128 CTAs.
// Stage: [Aq(64), Bh(128), Bl(128)] @272B rows.
// ---------------------------------------------------------------------------
#define G2_TA    (64 * 272)            // 17408
#define G2_TB    (128 * 272)           // 34816
#define G2_STAGE (G2_TA + 2 * G2_TB)   // 87040
#define G2_SMEM  (2 * G2_STAGE)        // 174080

__global__ __launch_bounds__(256, 1) void gemm2_mma_kernel(
    const float* __restrict__ b2, float* __restrict__ z_out)
{
    extern __shared__ char smem[];
    const uint32_t sb = smem_u32(smem);
    const int tid = threadIdx.x;
    const int wid = tid >> 5;
    const int lane = tid & 31;
    const int wm = wid & 1, wn = wid >> 1;   // 2x4 warps, warp tile 32x32
    const int rb = blockIdx.x;

    const __half* aq = g_hn_h + (size_t)(rb * 64) * HID;

    cp_t256<64, 256> (aq,      HID, sb + 0,             tid);
    cp_t256<128, 256>(g_w2t_h, HID, sb + G2_TA,         tid);
    cp_t256<128, 256>(g_w2t_l, HID, sb + G2_TA + G2_TB, tid);
    CP_COMMIT();

    const uint32_t lrow = (uint32_t)(lane & 15);
    const uint32_t lcol = (uint32_t)(lane >> 4) * 16;
    const uint32_t aoff = (uint32_t)(wm * 32) * 272 + lrow * 272 + lcol;
    const uint32_t boff = (uint32_t)(wn * 32) * 272 + lrow * 272 + lcol;

    float acc[2 * 4 * 4] = {};

    for (int kt = 0; kt < 4; ++kt) {
        if (kt < 3) {
            const int k0 = (kt + 1) * 128;
            const uint32_t st = sb + ((kt + 1) & 1) * G2_STAGE;
            cp_t256<64, 256> (aq + k0,      HID, st + 0,             tid);
            cp_t256<128, 256>(g_w2t_h + k0, HID, st + G2_TA,         tid);
            cp_t256<128, 256>(g_w2t_l + k0, HID, st + G2_TA + G2_TB, tid);
            CP_COMMIT();
            CP_WAIT(1);
        } else {
            CP_WAIT(0);
        }
        __syncthreads();
        const uint32_t st = sb + (kt & 1) * G2_STAGE;
        mma2<272, 8, 2, 4>(st + aoff, st + G2_TA + boff,
                           st + G2_TA + G2_TB + boff, acc);
        __syncthreads();
    }

    float* Cs = (float*)smem;
    stage_acc<2, 4>(Cs, acc, wm, wn, lane);
    __syncthreads();

    if (tid < 64) {
        const int r = tid;
        const int grow = rb * 64 + r;
        float s = 0.f;
#pragma unroll 8
        for (int c = 0; c < 128; ++c) {
            const float v = Cs[r * 133 + c] + b2[c];
            Cs[r * 133 + c] = v;
            s += v * v;
        }
        const float inv = 1.0f / fmaxf(sqrtf(s), 1e-8f);
#pragma unroll 8
        for (int c = 0; c < 128; ++c) {
            const float v = Cs[r * 133 + c];
            z_out[grow * OUT + c] = v;
            const float zn = v * inv;
            const __half hi = __float2half(zn);
            g_zn_h[grow * OUT + c] = hi;
            g_zn_l[grow * OUT + c] = __float2half(zn - __half2float(hi));
        }
    }
}

// ---------------------------------------------------------------------------
// Kernel 4: y_hat = zn @ zn^T. A side = zn_h (quantized), B side = hi+lo.
// 256 threads (8 warps 4x2, warp tile 32x64). Each CTA: one bi row-band,
// up to 4 j-tiles; A resident, B (hi,lo) double-buffered.
// ---------------------------------------------------------------------------
#define GR_TILE  (128 * 272)           // 34816
#define GR_A     GR_TILE               // A = zn_h band only
#define GR_BSTG  (2 * GR_TILE)         // [Bh, Bl]
#define GR_SMEM  (GR_A + 2 * GR_BSTG)  // 174080
#define NT       (B / 128)             // 64
#define JPC      4

__global__ __launch_bounds__(256, 1) void gram_mma_kernel(float* __restrict__ yhat)
{
    int t = blockIdx.x;
    int bi = 0;
    for (; bi < NT; ++bi) {
        const int c = (NT - bi + JPC - 1) >> 2;
        if (t < c) break;
        t -= c;
    }
    const int j0 = bi + t * JPC;
    const int count = min(JPC, NT - j0);

    extern __shared__ char smem[];
    const uint32_t sb = smem_u32(smem);
    const int tid = threadIdx.x;
    const int wid = tid >> 5;
    const int lane = tid & 31;
    const int wm = wid & 3, wn = wid >> 2;

    cp_t256<128, 256>(g_zn_h + (size_t)(bi * 128) * OUT, OUT, sb, tid);
    cp_t256<128, 256>(g_zn_h + (size_t)(j0 * 128) * OUT, OUT,
                      sb + GR_A + 0 * GR_TILE, tid);
    cp_t256<128, 256>(g_zn_l + (size_t)(j0 * 128) * OUT, OUT,
                      sb + GR_A + 1 * GR_TILE, tid);
    CP_COMMIT();
    if (count > 1) {
        cp_t256<128, 256>(g_zn_h + (size_t)((j0 + 1) * 128) * OUT, OUT,
                          sb + GR_A + GR_BSTG + 0 * GR_TILE, tid);
        cp_t256<128, 256>(g_zn_l + (size_t)((j0 + 1) * 128) * OUT, OUT,
                          sb + GR_A + GR_BSTG + 1 * GR_TILE, tid);
        CP_COMMIT();
    }

    const uint32_t lrow = (uint32_t)(lane & 15);
    const uint32_t lcol = (uint32_t)(lane >> 4) * 16;
    const uint32_t aoff = (uint32_t)(wm * 32) * 272 + lrow * 272 + lcol;
    const uint32_t boff = (uint32_t)(wn * 64) * 272 + lrow * 272 + lcol;

    for (int jj = 0; jj < count; ++jj) {
        const int p = jj & 1;
        const int bj = j0 + jj;
        const uint32_t bst = sb + GR_A + p * GR_BSTG;

        if (jj + 1 < count) { CP_WAIT(1); } else { CP_WAIT(0); }
        __syncthreads();

        float acc[2 * 8 * 4] = {};
        mma2<272, 8, 2, 8>(sb + aoff, bst + boff, bst + GR_TILE + boff, acc);
        __syncthreads();

        float* Cs = (float*)(smem + GR_A + p * GR_BSTG);  // consumed B stage
        stage_acc<2, 8>(Cs, acc, wm, wn, lane);
        __syncthreads();

        const long rowD = (long)bi * 128;
        const long colD = (long)bj * 128;
#pragma unroll
        for (int it = 0; it < 64; ++it) {
            const int idx = tid + it * 256;
            const int r = idx >> 7, c = idx & 127;
            yhat[(rowD + r) * (long)B + colD + c] = Cs[r * 133 + c];
        }
        if (bi != bj) {
#pragma unroll
            for (int it = 0; it < 64; ++it) {
                const int idx = tid + it * 256;
                const int r = idx >> 7, c = idx & 127;
                yhat[(colD + r) * (long)B + rowD + c] = Cs[c * 133 + r];
            }
        }
        __syncthreads();

        if (jj + 2 < count) {
            cp_t256<128, 256>(g_zn_h + ((long)(j0 + jj + 2) * 128) * OUT, OUT,
                              sb + GR_A + p * GR_BSTG + 0 * GR_TILE, tid);
            cp_t256<128, 256>(g_zn_l + ((long)(j0 + jj + 2) * 128) * OUT, OUT,
                              sb + GR_A + p * GR_BSTG + 1 * GR_TILE, tid);
            CP_COMMIT();
        }
    }
}

#define GRAM_GRID 544   // sum over bi of ceil((NT-bi)/JPC)

// ---------------------------------------------------------------------------
extern "C" void kernel_launch(void* const* d_in, const int* in_sizes, int n_in,
                              void* d_out, int out_size)
{
    const float* x       = (const float*)d_in[0];
    const float* w1      = (const float*)d_in[1];
    const float* b1      = (const float*)d_in[2];
    const float* prelu_a = (const float*)d_in[3];
    const float* gamma   = (const float*)d_in[4];
    const float* beta    = (const float*)d_in[5];
    const float* w2      = (const float*)d_in[6];
    const float* b2      = (const float*)d_in[7];

    float* out   = (float*)d_out;
    float* z_out = out;                    // [8192, 128]
    float* yhat  = out + (size_t)B * OUT;  // [8192, 8192]

    cudaFuncSetAttribute(gemm1_mma_kernel, cudaFuncAttributeMaxDynamicSharedMemorySize, G1_SMEM);
    cudaFuncSetAttribute(gemm2_mma_kernel, cudaFuncAttributeMaxDynamicSharedMemorySize, G2_SMEM);
    cudaFuncSetAttribute(gram_mma_kernel,  cudaFuncAttributeMaxDynamicSharedMemorySize, GR_SMEM);

    split_x_kernel<<<(B * IN_DIM / 2) / 256, 256>>>(x);
    split_w1t_kernel<<<(HID * IN_DIM) / 256, 256>>>(w1);
    split_w2t_kernel<<<(OUT * HID) / 256, 256>>>(w2);

    gemm1_mma_kernel<<<dim3(HID / 128, B / 128), 256, G1_SMEM>>>(b1, prelu_a);
    ln_split_kernel<<<B, 128>>>(gamma, beta);
    gemm2_mma_kernel<<<B / 64, 256, G2_SMEM>>>(b2, z_out);
    gram_mma_kernel<<<GRAM_GRID, 256, GR_SMEM>>>(yhat);
}

// round 12
// speedup vs baseline: 1.2959x; 1.0372x over previous
#include <cuda_runtime.h>
#include <cuda_fp16.h>
#include <math.h>
#include <cstdint>

#define B      8192
#define IN_DIM 1024
#define HID    512
#define OUT    128

// scratch (device globals — no allocation allowed)
__device__ float g_h[B * HID];                               // 16 MB
__device__ __align__(256) __half g_x_h[B * IN_DIM];          // 16 MB (fp16 x)
__device__ __align__(256) __half g_w1t_h[HID * IN_DIM];      // [n][k] hi
__device__ __align__(256) __half g_w1t_l[HID * IN_DIM];      // [n][k] lo
__device__ __align__(256) __half g_hn_h[B * HID];            // 8 MB (fp16 hn)
__device__ __align__(256) __half g_w2t_h[OUT * HID];         // [n][k] hi
__device__ __align__(256) __half g_w2t_l[OUT * HID];         // [n][k] lo
__device__ __align__(256) __half g_zn_h[B * OUT];            // 2 MB hi
__device__ __align__(256) __half g_zn_l[B * OUT];            // 2 MB lo

__device__ __forceinline__ uint32_t smem_u32(const void* p) {
    uint32_t a;
    asm("{ .reg .u64 t; cvta.to.shared.u64 t, %1; cvt.u32.u64 %0, t; }"
        : "=r"(a) : "l"(p));
    return a;
}

#define LDSM_X4(r0, r1, r2, r3, addr) \
    asm volatile("ldmatrix.sync.aligned.m8n8.x4.shared.b16 {%0,%1,%2,%3}, [%4];" \
        : "=r"(r0), "=r"(r1), "=r"(r2), "=r"(r3) : "r"(addr))

#define MMA_F16(d, a, b0, b1) \
    asm volatile("mma.sync.aligned.m16n8k16.row.col.f32.f16.f16.f32 " \
        "{%0,%1,%2,%3}, {%4,%5,%6,%7}, {%8,%9}, {%0,%1,%2,%3};" \
        : "+f"((d)[0]), "+f"((d)[1]), "+f"((d)[2]), "+f"((d)[3]) \
        : "r"((a)[0]), "r"((a)[1]), "r"((a)[2]), "r"((a)[3]), "r"(b0), "r"(b1))

#define CP16(dst, src) \
    asm volatile("cp.async.cg.shared.global [%0], [%1], 16;" \
        :: "r"(dst), "l"(src) : "memory")
#define CP_COMMIT() asm volatile("cp.async.commit_group;" ::: "memory")
#define CP_WAIT(n)  asm volatile("cp.async.wait_group %0;" :: "n"(n) : "memory")

// ---------------------------------------------------------------------------
// templated helpers
// ---------------------------------------------------------------------------
// 2-product HMMA over one K-chunk: A_q * (B_hi + B_lo). Fragments loaded once
// per k16-step. RB = smem row stride bytes, NKS = k16 steps, NM/NJ = frags.
template<int RB, int NKS, int NM, int NJ>
__device__ __forceinline__ void mma2(uint32_t aQ, uint32_t bH, uint32_t bL,
                                     float* acc)
{
#pragma unroll
    for (int ks = 0; ks < NKS; ++ks) {
        const uint32_t kb = (uint32_t)ks * 32;
        uint32_t a[NM][4];
#pragma unroll
        for (int i = 0; i < NM; ++i)
            LDSM_X4(a[i][0], a[i][1], a[i][2], a[i][3],
                    aQ + (uint32_t)i * 16 * RB + kb);
        uint32_t bh[NJ][2], bl[NJ][2];
#pragma unroll
        for (int p = 0; p < NJ / 2; ++p) {
            uint32_t r0, r1, r2, r3;
            LDSM_X4(r0, r1, r2, r3, bH + (uint32_t)p * 16 * RB + kb);
            bh[2 * p + 0][0] = r0; bh[2 * p + 0][1] = r2;
            bh[2 * p + 1][0] = r1; bh[2 * p + 1][1] = r3;
            LDSM_X4(r0, r1, r2, r3, bL + (uint32_t)p * 16 * RB + kb);
            bl[2 * p + 0][0] = r0; bl[2 * p + 0][1] = r2;
            bl[2 * p + 1][0] = r1; bl[2 * p + 1][1] = r3;
        }
#pragma unroll
        for (int i = 0; i < NM; ++i)
#pragma unroll
            for (int j = 0; j < NJ; ++j)
                MMA_F16(&acc[(i * NJ + j) * 4], a[i], bh[j][0], bh[j][1]);
#pragma unroll
        for (int i = 0; i < NM; ++i)
#pragma unroll
            for (int j = 0; j < NJ; ++j)
                MMA_F16(&acc[(i * NJ + j) * 4], a[i], bl[j][0], bl[j][1]);
    }
}

// stage acc fragments into Cs (stride 133 floats)
template<int NM, int NJ>
__device__ __forceinline__ void stage_acc(
    float* Cs, const float* acc, int wm, int wn, int lane)
{
#pragma unroll
    for (int i = 0; i < NM; ++i) {
        const int r0 = wm * (NM * 16) + i * 16 + (lane >> 2);
#pragma unroll
        for (int j = 0; j < NJ; ++j) {
            const int c0 = wn * (NJ * 8) + j * 8 + (lane & 3) * 2;
            const float* f = &acc[(i * NJ + j) * 4];
            Cs[r0 * 133 + c0]           = f[0];
            Cs[r0 * 133 + c0 + 1]       = f[1];
            Cs[(r0 + 8) * 133 + c0]     = f[2];
            Cs[(r0 + 8) * 133 + c0 + 1] = f[3];
        }
    }
}

// cp.async ROWSx256B tile (RB=272)
template<int ROWS, int NTH>
__device__ __forceinline__ void cp_t256(
    const __half* __restrict__ g, int gstride, uint32_t dst, int tid)
{
#pragma unroll
    for (int it = 0; it < ROWS * 16 / NTH; ++it) {
        const int idx = tid + it * NTH;
        const int row = idx >> 4, c16 = idx & 15;
        CP16(dst + row * 272 + c16 * 16, g + row * gstride + c16 * 8);
    }
}
// cp.async ROWSx128B tile (RB=144)
template<int ROWS, int NTH>
__device__ __forceinline__ void cp_t128(
    const __half* __restrict__ g, int gstride, uint32_t dst, int tid)
{
#pragma unroll
    for (int it = 0; it < ROWS * 8 / NTH; ++it) {
        const int idx = tid + it * NTH;
        const int row = idx >> 3, c16 = idx & 7;
        CP16(dst + row * 144 + c16 * 16, g + row * gstride + c16 * 8);
    }
}

// ---------------------------------------------------------------------------
// Prologue kernels: quantize/split inputs to fp16 (weights transposed+split)
// ---------------------------------------------------------------------------
__global__ __launch_bounds__(256) void split_x_kernel(const float* __restrict__ x)
{
    const int idx = blockIdx.x * 256 + threadIdx.x;
    const float2 v = ((const float2*)x)[idx];
    g_x_h[2 * idx]     = __float2half(v.x);
    g_x_h[2 * idx + 1] = __float2half(v.y);
}

__global__ __launch_bounds__(256) void split_w1t_kernel(const float* __restrict__ w1)
{
    const int idx = blockIdx.x * 256 + threadIdx.x;
    const int n = idx >> 10, k = idx & 1023;
    const float v = w1[k * HID + n];
    const __half h = __float2half(v);
    g_w1t_h[idx] = h;
    g_w1t_l[idx] = __float2half(v - __half2float(h));
}

__global__ __launch_bounds__(256) void split_w2t_kernel(const float* __restrict__ w2)
{
    const int idx = blockIdx.x * 256 + threadIdx.x;
    const int n = idx >> 9, k = idx & 511;
    const float v = w2[k * OUT + n];
    const __half h = __float2half(v);
    g_w2t_h[idx] = h;
    g_w2t_l[idx] = __float2half(v - __half2float(h));
}

// ---------------------------------------------------------------------------
// Kernel 1: h = PReLU(x @ w1 + b1). tile 256x128, BK=64, 2-stage cp.async,
// 256 threads (8 warps 4x2, warp tile 64x64, NM=4/NJ=8). grid = 4 x 32.
// ---------------------------------------------------------------------------
#define G1_TA    (256 * 144)          // 36864
#define G1_TB    (128 * 144)          // 18432
#define G1_STAGE (G1_TA + 2 * G1_TB)  // 73728: [Aq, Bh, Bl]
#define G1_SMEM  (2 * G1_STAGE)       // 147456

__global__ __launch_bounds__(256, 1) void gemm1_mma_kernel(
    const float* __restrict__ b1, const float* __restrict__ prelu_a)
{
    extern __shared__ char smem[];
    const uint32_t sb = smem_u32(smem);
    const int tid = threadIdx.x;
    const int wid = tid >> 5;
    const int lane = tid & 31;
    const int wm = wid & 3, wn = wid >> 2;   // 4x2 warps, warp tile 64x64
    const int rb = blockIdx.y, cb = blockIdx.x;

    const __half* xq = g_x_h   + (size_t)(rb * 256) * IN_DIM;
    const __half* wh = g_w1t_h + (size_t)(cb * 128) * IN_DIM;
    const __half* wl = g_w1t_l + (size_t)(cb * 128) * IN_DIM;

    cp_t128<256, 256>(xq, IN_DIM, sb + 0,             tid);
    cp_t128<128, 256>(wh, IN_DIM, sb + G1_TA,         tid);
    cp_t128<128, 256>(wl, IN_DIM, sb + G1_TA + G1_TB, tid);
    CP_COMMIT();

    const uint32_t lrow = (uint32_t)(lane & 15);
    const uint32_t lcol = (uint32_t)(lane >> 4) * 16;
    const uint32_t aoff = (uint32_t)(wm * 64) * 144 + lrow * 144 + lcol;
    const uint32_t boff = (uint32_t)(wn * 64) * 144 + lrow * 144 + lcol;

    float acc[4 * 8 * 4] = {};

    for (int kt = 0; kt < 16; ++kt) {
        if (kt < 15) {
            const int k0 = (kt + 1) * 64;
            const uint32_t st = sb + ((kt + 1) & 1) * G1_STAGE;
            cp_t128<256, 256>(xq + k0, IN_DIM, st + 0,             tid);
            cp_t128<128, 256>(wh + k0, IN_DIM, st + G1_TA,         tid);
            cp_t128<128, 256>(wl + k0, IN_DIM, st + G1_TA + G1_TB, tid);
            CP_COMMIT();
            CP_WAIT(1);
        } else {
            CP_WAIT(0);
        }
        __syncthreads();
        const uint32_t st = sb + (kt & 1) * G1_STAGE;
        mma2<144, 4, 4, 8>(st + aoff, st + G1_TA + boff,
                           st + G1_TA + G1_TB + boff, acc);
        __syncthreads();
    }

    float* Cs = (float*)smem;   // 256 x 133 floats = 136192 <= 147456
    stage_acc<4, 8>(Cs, acc, wm, wn, lane);
    __syncthreads();

    const float alpha = prelu_a[0];
#pragma unroll
    for (int it = 0; it < 128; ++it) {
        const int idx = tid + it * 256;
        const int r = idx >> 7, c = idx & 127;
        float v = Cs[r * 133 + c] + b1[cb * 128 + c];
        v = (v >= 0.0f) ? v : alpha * v;
        g_h[(size_t)(rb * 256 + r) * HID + cb * 128 + c] = v;
    }
}

// ---------------------------------------------------------------------------
// Kernel 2: LayerNorm rows of g_h -> hn quantized fp16 (float4 loads)
// ---------------------------------------------------------------------------
__global__ __launch_bounds__(128) void ln_split_kernel(
    const float* __restrict__ gamma, const float* __restrict__ beta)
{
    const int row = blockIdx.x;
    const float4* hp = (const float4*)(g_h + (size_t)row * HID);
    const int tid = threadIdx.x;

    const float4 v4 = hp[tid];
    float s  = v4.x + v4.y + v4.z + v4.w;
    float ss = v4.x * v4.x + v4.y * v4.y + v4.z * v4.z + v4.w * v4.w;
#pragma unroll
    for (int o = 16; o > 0; o >>= 1) {
        s  += __shfl_xor_sync(0xFFFFFFFFu, s,  o);
        ss += __shfl_xor_sync(0xFFFFFFFFu, ss, o);
    }
    __shared__ float sm[4], sm2[4];
    if ((tid & 31) == 0) { sm[tid >> 5] = s; sm2[tid >> 5] = ss; }
    __syncthreads();
    s  = sm[0]  + sm[1]  + sm[2]  + sm[3];
    ss = sm2[0] + sm2[1] + sm2[2] + sm2[3];

    const float mu   = s * (1.0f / HID);
    const float var  = ss * (1.0f / HID) - mu * mu;
    const float rstd = rsqrtf(var + 1e-6f);

    const float4 g4 = ((const float4*)gamma)[tid];
    const float4 b4 = ((const float4*)beta)[tid];
    __half2 o01 = __floats2half2_rn((v4.x - mu) * rstd * g4.x + b4.x,
                                    (v4.y - mu) * rstd * g4.y + b4.y);
    __half2 o23 = __floats2half2_rn((v4.z - mu) * rstd * g4.z + b4.z,
                                    (v4.w - mu) * rstd * g4.w + b4.w);
    uint2 packed;
    packed.x = *(uint32_t*)&o01;
    packed.y = *(uint32_t*)&o23;
    ((uint2*)(g_hn_h + (size_t)row * HID))[tid] = packed;
}

// ---------------------------------------------------------------------------
// Kernel 3: z = hn_q @ w2 + b2; epilogue row-norm + zn hi/lo split.
// tile 64x128, BK=128, 2-stage cp.async. 256 threads. grid = 128 CTAs.
// ---------------------------------------------------------------------------
#define G2_TA    (64 * 272)            // 17408
#define G2_TB    (128 * 272)           // 34816
#define G2_STAGE (G2_TA + 2 * G2_TB)   // 87040
#define G2_SMEM  (2 * G2_STAGE)        // 174080

__global__ __launch_bounds__(256, 1) void gemm2_mma_kernel(
    const float* __restrict__ b2, float* __restrict__ z_out)
{
    extern __shared__ char smem[];
    const uint32_t sb = smem_u32(smem);
    const int tid = threadIdx.x;
    const int wid = tid >> 5;
    const int lane = tid & 31;
    const int wm = wid & 1, wn = wid >> 1;   // 2x4 warps, warp tile 32x32
    const int rb = blockIdx.x;

    const __half* aq = g_hn_h + (size_t)(rb * 64) * HID;

    cp_t256<64, 256> (aq,      HID, sb + 0,             tid);
    cp_t256<128, 256>(g_w2t_h, HID, sb + G2_TA,         tid);
    cp_t256<128, 256>(g_w2t_l, HID, sb + G2_TA + G2_TB, tid);
    CP_COMMIT();

    const uint32_t lrow = (uint32_t)(lane & 15);
    const uint32_t lcol = (uint32_t)(lane >> 4) * 16;
    const uint32_t aoff = (uint32_t)(wm * 32) * 272 + lrow * 272 + lcol;
    const uint32_t boff = (uint32_t)(wn * 32) * 272 + lrow * 272 + lcol;

    float acc[2 * 4 * 4] = {};

    for (int kt = 0; kt < 4; ++kt) {
        if (kt < 3) {
            const int k0 = (kt + 1) * 128;
            const uint32_t st = sb + ((kt + 1) & 1) * G2_STAGE;
            cp_t256<64, 256> (aq + k0,      HID, st + 0,             tid);
            cp_t256<128, 256>(g_w2t_h + k0, HID, st + G2_TA,         tid);
            cp_t256<128, 256>(g_w2t_l + k0, HID, st + G2_TA + G2_TB, tid);
            CP_COMMIT();
            CP_WAIT(1);
        } else {
            CP_WAIT(0);
        }
        __syncthreads();
        const uint32_t st = sb + (kt & 1) * G2_STAGE;
        mma2<272, 8, 2, 4>(st + aoff, st + G2_TA + boff,
                           st + G2_TA + G2_TB + boff, acc);
        __syncthreads();
    }

    float* Cs = (float*)smem;
    stage_acc<2, 4>(Cs, acc, wm, wn, lane);
    __syncthreads();

    if (tid < 64) {
        const int r = tid;
        const int grow = rb * 64 + r;
        float s = 0.f;
#pragma unroll 8
        for (int c = 0; c < 128; ++c) {
            const float v = Cs[r * 133 + c] + b2[c];
            Cs[r * 133 + c] = v;
            s += v * v;
        }
        const float inv = 1.0f / fmaxf(sqrtf(s), 1e-8f);
#pragma unroll 8
        for (int c = 0; c < 128; ++c) {
            const float v = Cs[r * 133 + c];
            z_out[grow * OUT + c] = v;
            const float zn = v * inv;
            const __half hi = __float2half(zn);
            g_zn_h[grow * OUT + c] = hi;
            g_zn_l[grow * OUT + c] = __float2half(zn - __half2float(hi));
        }
    }
}

// ---------------------------------------------------------------------------
// Kernel 4: y_hat = zn @ zn^T. A side = zn_h (quantized), B side = hi+lo.
// 256 threads (8 warps 2x4, warp tile 64x32, NM=4/NJ=4). Each CTA: one bi
// row-band, up to 4 j-tiles; A resident, B (hi,lo) double-buffered.
// ---------------------------------------------------------------------------
#define GR_TILE  (128 * 272)           // 34816
#define GR_A     GR_TILE               // A = zn_h band only
#define GR_BSTG  (2 * GR_TILE)         // [Bh, Bl]
#define GR_SMEM  (GR_A + 2 * GR_BSTG)  // 174080
#define NT       (B / 128)             // 64
#define JPC      4

__global__ __launch_bounds__(256, 1) void gram_mma_kernel(float* __restrict__ yhat)
{
    int t = blockIdx.x;
    int bi = 0;
    for (; bi < NT; ++bi) {
        const int c = (NT - bi + JPC - 1) >> 2;
        if (t < c) break;
        t -= c;
    }
    const int j0 = bi + t * JPC;
    const int count = min(JPC, NT - j0);

    extern __shared__ char smem[];
    const uint32_t sb = smem_u32(smem);
    const int tid = threadIdx.x;
    const int wid = tid >> 5;
    const int lane = tid & 31;
    const int wm = wid & 1, wn = wid >> 1;   // 2x4 warps, warp tile 64x32

    cp_t256<128, 256>(g_zn_h + (size_t)(bi * 128) * OUT, OUT, sb, tid);
    cp_t256<128, 256>(g_zn_h + (size_t)(j0 * 128) * OUT, OUT,
                      sb + GR_A + 0 * GR_TILE, tid);
    cp_t256<128, 256>(g_zn_l + (size_t)(j0 * 128) * OUT, OUT,
                      sb + GR_A + 1 * GR_TILE, tid);
    CP_COMMIT();
    if (count > 1) {
        cp_t256<128, 256>(g_zn_h + (size_t)((j0 + 1) * 128) * OUT, OUT,
                          sb + GR_A + GR_BSTG + 0 * GR_TILE, tid);
        cp_t256<128, 256>(g_zn_l + (size_t)((j0 + 1) * 128) * OUT, OUT,
                          sb + GR_A + GR_BSTG + 1 * GR_TILE, tid);
        CP_COMMIT();
    }

    const uint32_t lrow = (uint32_t)(lane & 15);
    const uint32_t lcol = (uint32_t)(lane >> 4) * 16;
    const uint32_t aoff = (uint32_t)(wm * 64) * 272 + lrow * 272 + lcol;
    const uint32_t boff = (uint32_t)(wn * 32) * 272 + lrow * 272 + lcol;

    for (int jj = 0; jj < count; ++jj) {
        const int p = jj & 1;
        const int bj = j0 + jj;
        const uint32_t bst = sb + GR_A + p * GR_BSTG;

        if (jj + 1 < count) { CP_WAIT(1); } else { CP_WAIT(0); }
        __syncthreads();

        float acc[4 * 4 * 4] = {};
        mma2<272, 8, 4, 4>(sb + aoff, bst + boff, bst + GR_TILE + boff, acc);
        __syncthreads();

        float* Cs = (float*)(smem + GR_A + p * GR_BSTG);  // consumed B stage
        stage_acc<4, 4>(Cs, acc, wm, wn, lane);
        __syncthreads();

        const long rowD = (long)bi * 128;
        const long colD = (long)bj * 128;
#pragma unroll
        for (int it = 0; it < 64; ++it) {
            const int idx = tid + it * 256;
            const int r = idx >> 7, c = idx & 127;
            yhat[(rowD + r) * (long)B + colD + c] = Cs[r * 133 + c];
        }
        if (bi != bj) {
#pragma unroll
            for (int it = 0; it < 64; ++it) {
                const int idx = tid + it * 256;
                const int r = idx >> 7, c = idx & 127;
                yhat[(colD + r) * (long)B + rowD + c] = Cs[c * 133 + r];
            }
        }
        __syncthreads();

        if (jj + 2 < count) {
            cp_t256<128, 256>(g_zn_h + ((long)(j0 + jj + 2) * 128) * OUT, OUT,
                              sb + GR_A + p * GR_BSTG + 0 * GR_TILE, tid);
            cp_t256<128, 256>(g_zn_l + ((long)(j0 + jj + 2) * 128) * OUT, OUT,
                              sb + GR_A + p * GR_BSTG + 1 * GR_TILE, tid);
            CP_COMMIT();
        }
    }
}

#define GRAM_GRID 544   // sum over bi of ceil((NT-bi)/JPC)

// ---------------------------------------------------------------------------
extern "C" void kernel_launch(void* const* d_in, const int* in_sizes, int n_in,
                              void* d_out, int out_size)
{
    const float* x       = (const float*)d_in[0];
    const float* w1      = (const float*)d_in[1];
    const float* b1      = (const float*)d_in[2];
    const float* prelu_a = (const float*)d_in[3];
    const float* gamma   = (const float*)d_in[4];
    const float* beta    = (const float*)d_in[5];
    const float* w2      = (const float*)d_in[6];
    const float* b2      = (const float*)d_in[7];

    float* out   = (float*)d_out;
    float* z_out = out;                    // [8192, 128]
    float* yhat  = out + (size_t)B * OUT;  // [8192, 8192]

    cudaFuncSetAttribute(gemm1_mma_kernel, cudaFuncAttributeMaxDynamicSharedMemorySize, G1_SMEM);
    cudaFuncSetAttribute(gemm2_mma_kernel, cudaFuncAttributeMaxDynamicSharedMemorySize, G2_SMEM);
    cudaFuncSetAttribute(gram_mma_kernel,  cudaFuncAttributeMaxDynamicSharedMemorySize, GR_SMEM);

    split_x_kernel<<<(B * IN_DIM / 2) / 256, 256>>>(x);
    split_w1t_kernel<<<(HID * IN_DIM) / 256, 256>>>(w1);
    split_w2t_kernel<<<(OUT * HID) / 256, 256>>>(w2);

    gemm1_mma_kernel<<<dim3(HID / 128, B / 256), 256, G1_SMEM>>>(b1, prelu_a);
    ln_split_kernel<<<B, 128>>>(gamma, beta);
    gemm2_mma_kernel<<<B / 64, 256, G2_SMEM>>>(b2, z_out);
    gram_mma_kernel<<<GRAM_GRID, 256, GR_SMEM>>>(yhat);
}

// round 13
// speedup vs baseline: 1.4748x; 1.1381x over previous
#include <cuda_runtime.h>
#include <cuda_fp16.h>
#include <math.h>
#include <cstdint>

#define B      8192
#define IN_DIM 1024
#define HID    512
#define OUT    128

// scratch (device globals — no allocation allowed)
__device__ float g_h[B * HID];                               // 16 MB
__device__ __align__(256) __half g_x_h[B * IN_DIM];          // fp16 x
__device__ __align__(256) __half g_w1t_h[HID * IN_DIM];      // [n][k] fp16 w1^T
__device__ __align__(256) __half g_hn_h[B * HID];            // fp16 hn
__device__ __align__(256) __half g_w2t_h[OUT * HID];         // [n][k] fp16 w2^T
__device__ __align__(256) __half g_zn_h[B * OUT];            // zn hi
__device__ __align__(256) __half g_zn_l[B * OUT];            // zn lo

__device__ __forceinline__ uint32_t smem_u32(const void* p) {
    uint32_t a;
    asm("{ .reg .u64 t; cvta.to.shared.u64 t, %1; cvt.u32.u64 %0, t; }"
        : "=r"(a) : "l"(p));
    return a;
}

#define LDSM_X4(r0, r1, r2, r3, addr) \
    asm volatile("ldmatrix.sync.aligned.m8n8.x4.shared.b16 {%0,%1,%2,%3}, [%4];" \
        : "=r"(r0), "=r"(r1), "=r"(r2), "=r"(r3) : "r"(addr))

#define MMA_F16(d, a, b0, b1) \
    asm volatile("mma.sync.aligned.m16n8k16.row.col.f32.f16.f16.f32 " \
        "{%0,%1,%2,%3}, {%4,%5,%6,%7}, {%8,%9}, {%0,%1,%2,%3};" \
        : "+f"((d)[0]), "+f"((d)[1]), "+f"((d)[2]), "+f"((d)[3]) \
        : "r"((a)[0]), "r"((a)[1]), "r"((a)[2]), "r"((a)[3]), "r"(b0), "r"(b1))

#define CP16(dst, src) \
    asm volatile("cp.async.cg.shared.global [%0], [%1], 16;" \
        :: "r"(dst), "l"(src) : "memory")
#define CP_COMMIT() asm volatile("cp.async.commit_group;" ::: "memory")
#define CP_WAIT(n)  asm volatile("cp.async.wait_group %0;" :: "n"(n) : "memory")

// ---------------------------------------------------------------------------
// templated helpers
// ---------------------------------------------------------------------------
// single-product HMMA over one K-chunk: A_q * B_q
template<int RB, int NKS, int NM, int NJ>
__device__ __forceinline__ void mma1(uint32_t aQ, uint32_t bQ, float* acc)
{
#pragma unroll
    for (int ks = 0; ks < NKS; ++ks) {
        const uint32_t kb = (uint32_t)ks * 32;
        uint32_t a[NM][4];
#pragma unroll
        for (int i = 0; i < NM; ++i)
            LDSM_X4(a[i][0], a[i][1], a[i][2], a[i][3],
                    aQ + (uint32_t)i * 16 * RB + kb);
        uint32_t b[NJ][2];
#pragma unroll
        for (int p = 0; p < NJ / 2; ++p) {
            uint32_t r0, r1, r2, r3;
            LDSM_X4(r0, r1, r2, r3, bQ + (uint32_t)p * 16 * RB + kb);
            b[2 * p + 0][0] = r0; b[2 * p + 0][1] = r2;
            b[2 * p + 1][0] = r1; b[2 * p + 1][1] = r3;
        }
#pragma unroll
        for (int i = 0; i < NM; ++i)
#pragma unroll
            for (int j = 0; j < NJ; ++j)
                MMA_F16(&acc[(i * NJ + j) * 4], a[i], b[j][0], b[j][1]);
    }
}

// 2-product HMMA: A_q * (B_hi + B_lo) — used by the gram only
template<int RB, int NKS, int NM, int NJ>
__device__ __forceinline__ void mma2(uint32_t aQ, uint32_t bH, uint32_t bL,
                                     float* acc)
{
#pragma unroll
    for (int ks = 0; ks < NKS; ++ks) {
        const uint32_t kb = (uint32_t)ks * 32;
        uint32_t a[NM][4];
#pragma unroll
        for (int i = 0; i < NM; ++i)
            LDSM_X4(a[i][0], a[i][1], a[i][2], a[i][3],
                    aQ + (uint32_t)i * 16 * RB + kb);
        uint32_t bh[NJ][2], bl[NJ][2];
#pragma unroll
        for (int p = 0; p < NJ / 2; ++p) {
            uint32_t r0, r1, r2, r3;
            LDSM_X4(r0, r1, r2, r3, bH + (uint32_t)p * 16 * RB + kb);
            bh[2 * p + 0][0] = r0; bh[2 * p + 0][1] = r2;
            bh[2 * p + 1][0] = r1; bh[2 * p + 1][1] = r3;
            LDSM_X4(r0, r1, r2, r3, bL + (uint32_t)p * 16 * RB + kb);
            bl[2 * p + 0][0] = r0; bl[2 * p + 0][1] = r2;
            bl[2 * p + 1][0] = r1; bl[2 * p + 1][1] = r3;
        }
#pragma unroll
        for (int i = 0; i < NM; ++i)
#pragma unroll
            for (int j = 0; j < NJ; ++j)
                MMA_F16(&acc[(i * NJ + j) * 4], a[i], bh[j][0], bh[j][1]);
#pragma unroll
        for (int i = 0; i < NM; ++i)
#pragma unroll
            for (int j = 0; j < NJ; ++j)
                MMA_F16(&acc[(i * NJ + j) * 4], a[i], bl[j][0], bl[j][1]);
    }
}

// stage acc fragments into Cs (stride 133 floats)
template<int NM, int NJ>
__device__ __forceinline__ void stage_acc(
    float* Cs, const float* acc, int wm, int wn, int lane)
{
#pragma unroll
    for (int i = 0; i < NM; ++i) {
        const int r0 = wm * (NM * 16) + i * 16 + (lane >> 2);
#pragma unroll
        for (int j = 0; j < NJ; ++j) {
            const int c0 = wn * (NJ * 8) + j * 8 + (lane & 3) * 2;
            const float* f = &acc[(i * NJ + j) * 4];
            Cs[r0 * 133 + c0]           = f[0];
            Cs[r0 * 133 + c0 + 1]       = f[1];
            Cs[(r0 + 8) * 133 + c0]     = f[2];
            Cs[(r0 + 8) * 133 + c0 + 1] = f[3];
        }
    }
}

// cp.async ROWSx256B tile (RB=272)
template<int ROWS, int NTH>
__device__ __forceinline__ void cp_t256(
    const __half* __restrict__ g, int gstride, uint32_t dst, int tid)
{
#pragma unroll
    for (int it = 0; it < ROWS * 16 / NTH; ++it) {
        const int idx = tid + it * NTH;
        const int row = idx >> 4, c16 = idx & 15;
        CP16(dst + row * 272 + c16 * 16, g + row * gstride + c16 * 8);
    }
}
// cp.async ROWSx128B tile (RB=144)
template<int ROWS, int NTH>
__device__ __forceinline__ void cp_t128(
    const __half* __restrict__ g, int gstride, uint32_t dst, int tid)
{
#pragma unroll
    for (int it = 0; it < ROWS * 8 / NTH; ++it) {
        const int idx = tid + it * NTH;
        const int row = idx >> 3, c16 = idx & 7;
        CP16(dst + row * 144 + c16 * 16, g + row * gstride + c16 * 8);
    }
}

// ---------------------------------------------------------------------------
// Prologue kernels: quantize inputs to fp16 (weights transposed)
// ---------------------------------------------------------------------------
__global__ __launch_bounds__(256) void split_x_kernel(const float* __restrict__ x)
{
    const int idx = blockIdx.x * 256 + threadIdx.x;
    const float2 v = ((const float2*)x)[idx];
    g_x_h[2 * idx]     = __float2half(v.x);
    g_x_h[2 * idx + 1] = __float2half(v.y);
}

__global__ __launch_bounds__(256) void split_w1t_kernel(const float* __restrict__ w1)
{
    const int idx = blockIdx.x * 256 + threadIdx.x;
    const int n = idx >> 10, k = idx & 1023;
    g_w1t_h[idx] = __float2half(w1[k * HID + n]);
}

__global__ __launch_bounds__(256) void split_w2t_kernel(const float* __restrict__ w2)
{
    const int idx = blockIdx.x * 256 + threadIdx.x;
    const int n = idx >> 9, k = idx & 511;
    g_w2t_h[idx] = __float2half(w2[k * OUT + n]);
}

// ---------------------------------------------------------------------------
// Kernel 1: h = PReLU(x @ w1 + b1). Pure fp16 GEMM. tile 256x128, BK=64,
// 2-stage cp.async, 256 threads (8 warps 4x2, warp tile 64x64).
// ---------------------------------------------------------------------------
#define G1_TA    (256 * 144)          // 36864
#define G1_TB    (128 * 144)          // 18432
#define G1_STAGE (G1_TA + G1_TB)      // 55296: [Aq, Bq]
#define G1_SMEM  (2 * G1_STAGE)       // 110592

__global__ __launch_bounds__(256, 1) void gemm1_mma_kernel(
    const float* __restrict__ b1, const float* __restrict__ prelu_a)
{
    extern __shared__ char smem[];
    const uint32_t sb = smem_u32(smem);
    const int tid = threadIdx.x;
    const int wid = tid >> 5;
    const int lane = tid & 31;
    const int wm = wid & 3, wn = wid >> 2;   // 4x2 warps, warp tile 64x64
    const int rb = blockIdx.y, cb = blockIdx.x;

    const __half* xq = g_x_h   + (size_t)(rb * 256) * IN_DIM;
    const __half* wq = g_w1t_h + (size_t)(cb * 128) * IN_DIM;

    cp_t128<256, 256>(xq, IN_DIM, sb + 0,     tid);
    cp_t128<128, 256>(wq, IN_DIM, sb + G1_TA, tid);
    CP_COMMIT();

    const uint32_t lrow = (uint32_t)(lane & 15);
    const uint32_t lcol = (uint32_t)(lane >> 4) * 16;
    const uint32_t aoff = (uint32_t)(wm * 64) * 144 + lrow * 144 + lcol;
    const uint32_t boff = (uint32_t)(wn * 64) * 144 + lrow * 144 + lcol;

    float acc[4 * 8 * 4] = {};

    for (int kt = 0; kt < 16; ++kt) {
        if (kt < 15) {
            const int k0 = (kt + 1) * 64;
            const uint32_t st = sb + ((kt + 1) & 1) * G1_STAGE;
            cp_t128<256, 256>(xq + k0, IN_DIM, st + 0,     tid);
            cp_t128<128, 256>(wq + k0, IN_DIM, st + G1_TA, tid);
            CP_COMMIT();
            CP_WAIT(1);
        } else {
            CP_WAIT(0);
        }
        __syncthreads();
        const uint32_t st = sb + (kt & 1) * G1_STAGE;
        mma1<144, 4, 4, 8>(st + aoff, st + G1_TA + boff, acc);
        __syncthreads();
    }

    // epilogue: stage in two 128-row halves (Cs = 128x133 floats = 68096 <= smem)
    float* Cs = (float*)smem;
    const float alpha = prelu_a[0];
#pragma unroll
    for (int half = 0; half < 2; ++half) {
        // warps with wm in [half*2, half*2+2) own these 128 rows
        if ((wm >> 1) == half) {
            const int wml = wm & 1;   // local warp row within half
#pragma unroll
            for (int i = 0; i < 4; ++i) {
                const int r0 = wml * 64 + i * 16 + (lane >> 2);
#pragma unroll
                for (int j = 0; j < 8; ++j) {
                    const int c0 = wn * 64 + j * 8 + (lane & 3) * 2;
                    const float* f = &acc[(i * 8 + j) * 4];
                    Cs[r0 * 133 + c0]           = f[0];
                    Cs[r0 * 133 + c0 + 1]       = f[1];
                    Cs[(r0 + 8) * 133 + c0]     = f[2];
                    Cs[(r0 + 8) * 133 + c0 + 1] = f[3];
                }
            }
        }
        __syncthreads();
#pragma unroll
        for (int it = 0; it < 64; ++it) {
            const int idx = tid + it * 256;
            const int r = idx >> 7, c = idx & 127;
            float v = Cs[r * 133 + c] + b1[cb * 128 + c];
            v = (v >= 0.0f) ? v : alpha * v;
            g_h[(size_t)(rb * 256 + half * 128 + r) * HID + cb * 128 + c] = v;
        }
        __syncthreads();
    }
}

// ---------------------------------------------------------------------------
// Kernel 2: LayerNorm rows of g_h -> hn quantized fp16 (float4 loads)
// ---------------------------------------------------------------------------
__global__ __launch_bounds__(128) void ln_split_kernel(
    const float* __restrict__ gamma, const float* __restrict__ beta)
{
    const int row = blockIdx.x;
    const float4* hp = (const float4*)(g_h + (size_t)row * HID);
    const int tid = threadIdx.x;

    const float4 v4 = hp[tid];
    float s  = v4.x + v4.y + v4.z + v4.w;
    float ss = v4.x * v4.x + v4.y * v4.y + v4.z * v4.z + v4.w * v4.w;
#pragma unroll
    for (int o = 16; o > 0; o >>= 1) {
        s  += __shfl_xor_sync(0xFFFFFFFFu, s,  o);
        ss += __shfl_xor_sync(0xFFFFFFFFu, ss, o);
    }
    __shared__ float sm[4], sm2[4];
    if ((tid & 31) == 0) { sm[tid >> 5] = s; sm2[tid >> 5] = ss; }
    __syncthreads();
    s  = sm[0]  + sm[1]  + sm[2]  + sm[3];
    ss = sm2[0] + sm2[1] + sm2[2] + sm2[3];

    const float mu   = s * (1.0f / HID);
    const float var  = ss * (1.0f / HID) - mu * mu;
    const float rstd = rsqrtf(var + 1e-6f);

    const float4 g4 = ((const float4*)gamma)[tid];
    const float4 b4 = ((const float4*)beta)[tid];
    __half2 o01 = __floats2half2_rn((v4.x - mu) * rstd * g4.x + b4.x,
                                    (v4.y - mu) * rstd * g4.y + b4.y);
    __half2 o23 = __floats2half2_rn((v4.z - mu) * rstd * g4.z + b4.z,
                                    (v4.w - mu) * rstd * g4.w + b4.w);
    uint2 packed;
    packed.x = *(uint32_t*)&o01;
    packed.y = *(uint32_t*)&o23;
    ((uint2*)(g_hn_h + (size_t)row * HID))[tid] = packed;
}

// ---------------------------------------------------------------------------
// Kernel 3: z = hn_q @ w2_q + b2; epilogue row-norm + zn hi/lo split.
// tile 64x128, BK=128, 2-stage cp.async. 256 threads. grid = 128 CTAs.
// ---------------------------------------------------------------------------
#define G2_TA    (64 * 272)            // 17408
#define G2_TB    (128 * 272)           // 34816
#define G2_STAGE (G2_TA + G2_TB)       // 52224: [Aq, Bq]
#define G2_SMEM  (2 * G2_STAGE)        // 104448

__global__ __launch_bounds__(256, 1) void gemm2_mma_kernel(
    const float* __restrict__ b2, float* __restrict__ z_out)
{
    extern __shared__ char smem[];
    const uint32_t sb = smem_u32(smem);
    const int tid = threadIdx.x;
    const int wid = tid >> 5;
    const int lane = tid & 31;
    const int wm = wid & 1, wn = wid >> 1;   // 2x4 warps, warp tile 32x32
    const int rb = blockIdx.x;

    const __half* aq = g_hn_h + (size_t)(rb * 64) * HID;

    cp_t256<64, 256> (aq,      HID, sb + 0,     tid);
    cp_t256<128, 256>(g_w2t_h, HID, sb + G2_TA, tid);
    CP_COMMIT();

    const uint32_t lrow = (uint32_t)(lane & 15);
    const uint32_t lcol = (uint32_t)(lane >> 4) * 16;
    const uint32_t aoff = (uint32_t)(wm * 32) * 272 + lrow * 272 + lcol;
    const uint32_t boff = (uint32_t)(wn * 32) * 272 + lrow * 272 + lcol;

    float acc[2 * 4 * 4] = {};

    for (int kt = 0; kt < 4; ++kt) {
        if (kt < 3) {
            const int k0 = (kt + 1) * 128;
            const uint32_t st = sb + ((kt + 1) & 1) * G2_STAGE;
            cp_t256<64, 256> (aq + k0,      HID, st + 0,     tid);
            cp_t256<128, 256>(g_w2t_h + k0, HID, st + G2_TA, tid);
            CP_COMMIT();
            CP_WAIT(1);
        } else {
            CP_WAIT(0);
        }
        __syncthreads();
        const uint32_t st = sb + (kt & 1) * G2_STAGE;
        mma1<272, 8, 2, 4>(st + aoff, st + G2_TA + boff, acc);
        __syncthreads();
    }

    float* Cs = (float*)smem;
    stage_acc<2, 4>(Cs, acc, wm, wn, lane);
    __syncthreads();

    if (tid < 64) {
        const int r = tid;
        const int grow = rb * 64 + r;
        float s = 0.f;
#pragma unroll 8
        for (int c = 0; c < 128; ++c) {
            const float v = Cs[r * 133 + c] + b2[c];
            Cs[r * 133 + c] = v;
            s += v * v;
        }
        const float inv = 1.0f / fmaxf(sqrtf(s), 1e-8f);
#pragma unroll 8
        for (int c = 0; c < 128; ++c) {
            const float v = Cs[r * 133 + c];
            z_out[grow * OUT + c] = v;
            const float zn = v * inv;
            const __half hi = __float2half(zn);
            g_zn_h[grow * OUT + c] = hi;
            g_zn_l[grow * OUT + c] = __float2half(zn - __half2float(hi));
        }
    }
}

// ---------------------------------------------------------------------------
// Kernel 4: y_hat = zn @ zn^T. A side = zn_h (quantized), B side = hi+lo.
// 256 threads (8 warps 2x4, warp tile 64x32, NM=4/NJ=4). Each CTA: one bi
// row-band, up to 4 j-tiles; A resident, B (hi,lo) double-buffered.
// ---------------------------------------------------------------------------
#define GR_TILE  (128 * 272)           // 34816
#define GR_A     GR_TILE               // A = zn_h band only
#define GR_BSTG  (2 * GR_TILE)         // [Bh, Bl]
#define GR_SMEM  (GR_A + 2 * GR_BSTG)  // 174080
#define NT       (B / 128)             // 64
#define JPC      4

__global__ __launch_bounds__(256, 1) void gram_mma_kernel(float* __restrict__ yhat)
{
    int t = blockIdx.x;
    int bi = 0;
    for (; bi < NT; ++bi) {
        const int c = (NT - bi + JPC - 1) >> 2;
        if (t < c) break;
        t -= c;
    }
    const int j0 = bi + t * JPC;
    const int count = min(JPC, NT - j0);

    extern __shared__ char smem[];
    const uint32_t sb = smem_u32(smem);
    const int tid = threadIdx.x;
    const int wid = tid >> 5;
    const int lane = tid & 31;
    const int wm = wid & 1, wn = wid >> 1;   // 2x4 warps, warp tile 64x32

    cp_t256<128, 256>(g_zn_h + (size_t)(bi * 128) * OUT, OUT, sb, tid);
    cp_t256<128, 256>(g_zn_h + (size_t)(j0 * 128) * OUT, OUT,
                      sb + GR_A + 0 * GR_TILE, tid);
    cp_t256<128, 256>(g_zn_l + (size_t)(j0 * 128) * OUT, OUT,
                      sb + GR_A + 1 * GR_TILE, tid);
    CP_COMMIT();
    if (count > 1) {
        cp_t256<128, 256>(g_zn_h + (size_t)((j0 + 1) * 128) * OUT, OUT,
                          sb + GR_A + GR_BSTG + 0 * GR_TILE, tid);
        cp_t256<128, 256>(g_zn_l + (size_t)((j0 + 1) * 128) * OUT, OUT,
                          sb + GR_A + GR_BSTG + 1 * GR_TILE, tid);
        CP_COMMIT();
    }

    const uint32_t lrow = (uint32_t)(lane & 15);
    const uint32_t lcol = (uint32_t)(lane >> 4) * 16;
    const uint32_t aoff = (uint32_t)(wm * 64) * 272 + lrow * 272 + lcol;
    const uint32_t boff = (uint32_t)(wn * 32) * 272 + lrow * 272 + lcol;

    for (int jj = 0; jj < count; ++jj) {
        const int p = jj & 1;
        const int bj = j0 + jj;
        const uint32_t bst = sb + GR_A + p * GR_BSTG;

        if (jj + 1 < count) { CP_WAIT(1); } else { CP_WAIT(0); }
        __syncthreads();

        float acc[4 * 4 * 4] = {};
        mma2<272, 8, 4, 4>(sb + aoff, bst + boff, bst + GR_TILE + boff, acc);
        __syncthreads();

        float* Cs = (float*)(smem + GR_A + p * GR_BSTG);  // consumed B stage
        stage_acc<4, 4>(Cs, acc, wm, wn, lane);
        __syncthreads();

        const long rowD = (long)bi * 128;
        const long colD = (long)bj * 128;
#pragma unroll
        for (int it = 0; it < 64; ++it) {
            const int idx = tid + it * 256;
            const int r = idx >> 7, c = idx & 127;
            yhat[(rowD + r) * (long)B + colD + c] = Cs[r * 133 + c];
        }
        if (bi != bj) {
#pragma unroll
            for (int it = 0; it < 64; ++it) {
                const int idx = tid + it * 256;
                const int r = idx >> 7, c = idx & 127;
                yhat[(colD + r) * (long)B + rowD + c] = Cs[c * 133 + r];
            }
        }
        __syncthreads();

        if (jj + 2 < count) {
            cp_t256<128, 256>(g_zn_h + ((long)(j0 + jj + 2) * 128) * OUT, OUT,
                              sb + GR_A + p * GR_BSTG + 0 * GR_TILE, tid);
            cp_t256<128, 256>(g_zn_l + ((long)(j0 + jj + 2) * 128) * OUT, OUT,
                              sb + GR_A + p * GR_BSTG + 1 * GR_TILE, tid);
            CP_COMMIT();
        }
    }
}

#define GRAM_GRID 544   // sum over bi of ceil((NT-bi)/JPC)

// ---------------------------------------------------------------------------
extern "C" void kernel_launch(void* const* d_in, const int* in_sizes, int n_in,
                              void* d_out, int out_size)
{
    const float* x       = (const float*)d_in[0];
    const float* w1      = (const float*)d_in[1];
    const float* b1      = (const float*)d_in[2];
    const float* prelu_a = (const float*)d_in[3];
    const float* gamma   = (const float*)d_in[4];
    const float* beta    = (const float*)d_in[5];
    const float* w2      = (const float*)d_in[6];
    const float* b2      = (const float*)d_in[7];

    float* out   = (float*)d_out;
    float* z_out = out;                    // [8192, 128]
    float* yhat  = out + (size_t)B * OUT;  // [8192, 8192]

    cudaFuncSetAttribute(gemm1_mma_kernel, cudaFuncAttributeMaxDynamicSharedMemorySize, G1_SMEM);
    cudaFuncSetAttribute(gemm2_mma_kernel, cudaFuncAttributeMaxDynamicSharedMemorySize, G2_SMEM);
    cudaFuncSetAttribute(gram_mma_kernel,  cudaFuncAttributeMaxDynamicSharedMemorySize, GR_SMEM);

    split_x_kernel<<<(B * IN_DIM / 2) / 256, 256>>>(x);
    split_w1t_kernel<<<(HID * IN_DIM) / 256, 256>>>(w1);
    split_w2t_kernel<<<(OUT * HID) / 256, 256>>>(w2);

    gemm1_mma_kernel<<<dim3(HID / 128, B / 256), 256, G1_SMEM>>>(b1, prelu_a);
    ln_split_kernel<<<B, 128>>>(gamma, beta);
    gemm2_mma_kernel<<<B / 64, 256, G2_SMEM>>>(b2, z_out);
    gram_mma_kernel<<<GRAM_GRID, 256, GR_SMEM>>>(yhat);
}

// round 14
// speedup vs baseline: 1.7289x; 1.1723x over previous
#include <cuda_runtime.h>
#include <cuda_fp16.h>
#include <math.h>
#include <cstdint>

#define B      8192
#define IN_DIM 1024
#define HID    512
#define OUT    128

// scratch (device globals — no allocation allowed)
__device__ float g_h[B * HID];                               // 16 MB
__device__ __align__(256) __half g_x_h[B * IN_DIM];          // fp16 x
__device__ __align__(256) __half g_w1t_h[HID * IN_DIM];      // [n][k] fp16 w1^T
__device__ __align__(256) __half g_hn_h[B * HID];            // fp16 hn
__device__ __align__(256) __half g_w2t_h[OUT * HID];         // [n][k] fp16 w2^T
__device__ __align__(256) __half g_zn_h[B * OUT];            // fp16 zn

__device__ __forceinline__ uint32_t smem_u32(const void* p) {
    uint32_t a;
    asm("{ .reg .u64 t; cvta.to.shared.u64 t, %1; cvt.u32.u64 %0, t; }"
        : "=r"(a) : "l"(p));
    return a;
}

#define LDSM_X4(r0, r1, r2, r3, addr) \
    asm volatile("ldmatrix.sync.aligned.m8n8.x4.shared.b16 {%0,%1,%2,%3}, [%4];" \
        : "=r"(r0), "=r"(r1), "=r"(r2), "=r"(r3) : "r"(addr))

#define MMA_F16(d, a, b0, b1) \
    asm volatile("mma.sync.aligned.m16n8k16.row.col.f32.f16.f16.f32 " \
        "{%0,%1,%2,%3}, {%4,%5,%6,%7}, {%8,%9}, {%0,%1,%2,%3};" \
        : "+f"((d)[0]), "+f"((d)[1]), "+f"((d)[2]), "+f"((d)[3]) \
        : "r"((a)[0]), "r"((a)[1]), "r"((a)[2]), "r"((a)[3]), "r"(b0), "r"(b1))

#define CP16(dst, src) \
    asm volatile("cp.async.cg.shared.global [%0], [%1], 16;" \
        :: "r"(dst), "l"(src) : "memory")
#define CP_COMMIT() asm volatile("cp.async.commit_group;" ::: "memory")
#define CP_WAIT(n)  asm volatile("cp.async.wait_group %0;" :: "n"(n) : "memory")

// ---------------------------------------------------------------------------
// templated helpers
// ---------------------------------------------------------------------------
// single-product HMMA over one K-chunk: A_q * B_q
template<int RB, int NKS, int NM, int NJ>
__device__ __forceinline__ void mma1(uint32_t aQ, uint32_t bQ, float* acc)
{
#pragma unroll
    for (int ks = 0; ks < NKS; ++ks) {
        const uint32_t kb = (uint32_t)ks * 32;
        uint32_t a[NM][4];
#pragma unroll
        for (int i = 0; i < NM; ++i)
            LDSM_X4(a[i][0], a[i][1], a[i][2], a[i][3],
                    aQ + (uint32_t)i * 16 * RB + kb);
        uint32_t b[NJ][2];
#pragma unroll
        for (int p = 0; p < NJ / 2; ++p) {
            uint32_t r0, r1, r2, r3;
            LDSM_X4(r0, r1, r2, r3, bQ + (uint32_t)p * 16 * RB + kb);
            b[2 * p + 0][0] = r0; b[2 * p + 0][1] = r2;
            b[2 * p + 1][0] = r1; b[2 * p + 1][1] = r3;
        }
#pragma unroll
        for (int i = 0; i < NM; ++i)
#pragma unroll
            for (int j = 0; j < NJ; ++j)
                MMA_F16(&acc[(i * NJ + j) * 4], a[i], b[j][0], b[j][1]);
    }
}

// stage acc fragments into Cs (stride 133 floats)
template<int NM, int NJ>
__device__ __forceinline__ void stage_acc(
    float* Cs, const float* acc, int wm, int wn, int lane)
{
#pragma unroll
    for (int i = 0; i < NM; ++i) {
        const int r0 = wm * (NM * 16) + i * 16 + (lane >> 2);
#pragma unroll
        for (int j = 0; j < NJ; ++j) {
            const int c0 = wn * (NJ * 8) + j * 8 + (lane & 3) * 2;
            const float* f = &acc[(i * NJ + j) * 4];
            Cs[r0 * 133 + c0]           = f[0];
            Cs[r0 * 133 + c0 + 1]       = f[1];
            Cs[(r0 + 8) * 133 + c0]     = f[2];
            Cs[(r0 + 8) * 133 + c0 + 1] = f[3];
        }
    }
}

// cp.async ROWSx256B tile (RB=272)
template<int ROWS, int NTH>
__device__ __forceinline__ void cp_t256(
    const __half* __restrict__ g, int gstride, uint32_t dst, int tid)
{
#pragma unroll
    for (int it = 0; it < ROWS * 16 / NTH; ++it) {
        const int idx = tid + it * NTH;
        const int row = idx >> 4, c16 = idx & 15;
        CP16(dst + row * 272 + c16 * 16, g + row * gstride + c16 * 8);
    }
}
// cp.async ROWSx128B tile (RB=144)
template<int ROWS, int NTH>
__device__ __forceinline__ void cp_t128(
    const __half* __restrict__ g, int gstride, uint32_t dst, int tid)
{
#pragma unroll
    for (int it = 0; it < ROWS * 8 / NTH; ++it) {
        const int idx = tid + it * NTH;
        const int row = idx >> 3, c16 = idx & 7;
        CP16(dst + row * 144 + c16 * 16, g + row * gstride + c16 * 8);
    }
}

// ---------------------------------------------------------------------------
// Prologue kernels: quantize inputs to fp16 (weights transposed)
// ---------------------------------------------------------------------------
__global__ __launch_bounds__(256) void split_x_kernel(const float* __restrict__ x)
{
    const int idx = blockIdx.x * 256 + threadIdx.x;
    const float2 v = ((const float2*)x)[idx];
    g_x_h[2 * idx]     = __float2half(v.x);
    g_x_h[2 * idx + 1] = __float2half(v.y);
}

__global__ __launch_bounds__(256) void split_w1t_kernel(const float* __restrict__ w1)
{
    const int idx = blockIdx.x * 256 + threadIdx.x;
    const int n = idx >> 10, k = idx & 1023;
    g_w1t_h[idx] = __float2half(w1[k * HID + n]);
}

__global__ __launch_bounds__(256) void split_w2t_kernel(const float* __restrict__ w2)
{
    const int idx = blockIdx.x * 256 + threadIdx.x;
    const int n = idx >> 9, k = idx & 511;
    g_w2t_h[idx] = __float2half(w2[k * OUT + n]);
}

// ---------------------------------------------------------------------------
// Kernel 1: h = PReLU(x @ w1 + b1). Pure fp16 GEMM. tile 256x128, BK=64,
// 2-stage cp.async, 256 threads (8 warps 4x2, warp tile 64x64).
// ---------------------------------------------------------------------------
#define G1_TA    (256 * 144)          // 36864
#define G1_TB    (128 * 144)          // 18432
#define G1_STAGE (G1_TA + G1_TB)      // 55296: [Aq, Bq]
#define G1_SMEM  (2 * G1_STAGE)       // 110592

__global__ __launch_bounds__(256, 1) void gemm1_mma_kernel(
    const float* __restrict__ b1, const float* __restrict__ prelu_a)
{
    extern __shared__ char smem[];
    const uint32_t sb = smem_u32(smem);
    const int tid = threadIdx.x;
    const int wid = tid >> 5;
    const int lane = tid & 31;
    const int wm = wid & 3, wn = wid >> 2;   // 4x2 warps, warp tile 64x64
    const int rb = blockIdx.y, cb = blockIdx.x;

    const __half* xq = g_x_h   + (size_t)(rb * 256) * IN_DIM;
    const __half* wq = g_w1t_h + (size_t)(cb * 128) * IN_DIM;

    cp_t128<256, 256>(xq, IN_DIM, sb + 0,     tid);
    cp_t128<128, 256>(wq, IN_DIM, sb + G1_TA, tid);
    CP_COMMIT();

    const uint32_t lrow = (uint32_t)(lane & 15);
    const uint32_t lcol = (uint32_t)(lane >> 4) * 16;
    const uint32_t aoff = (uint32_t)(wm * 64) * 144 + lrow * 144 + lcol;
    const uint32_t boff = (uint32_t)(wn * 64) * 144 + lrow * 144 + lcol;

    float acc[4 * 8 * 4] = {};

    for (int kt = 0; kt < 16; ++kt) {
        if (kt < 15) {
            const int k0 = (kt + 1) * 64;
            const uint32_t st = sb + ((kt + 1) & 1) * G1_STAGE;
            cp_t128<256, 256>(xq + k0, IN_DIM, st + 0,     tid);
            cp_t128<128, 256>(wq + k0, IN_DIM, st + G1_TA, tid);
            CP_COMMIT();
            CP_WAIT(1);
        } else {
            CP_WAIT(0);
        }
        __syncthreads();
        const uint32_t st = sb + (kt & 1) * G1_STAGE;
        mma1<144, 4, 4, 8>(st + aoff, st + G1_TA + boff, acc);
        __syncthreads();
    }

    // epilogue: stage in two 128-row halves
    float* Cs = (float*)smem;
    const float alpha = prelu_a[0];
#pragma unroll
    for (int half = 0; half < 2; ++half) {
        if ((wm >> 1) == half) {
            const int wml = wm & 1;
#pragma unroll
            for (int i = 0; i < 4; ++i) {
                const int r0 = wml * 64 + i * 16 + (lane >> 2);
#pragma unroll
                for (int j = 0; j < 8; ++j) {
                    const int c0 = wn * 64 + j * 8 + (lane & 3) * 2;
                    const float* f = &acc[(i * 8 + j) * 4];
                    Cs[r0 * 133 + c0]           = f[0];
                    Cs[r0 * 133 + c0 + 1]       = f[1];
                    Cs[(r0 + 8) * 133 + c0]     = f[2];
                    Cs[(r0 + 8) * 133 + c0 + 1] = f[3];
                }
            }
        }
        __syncthreads();
#pragma unroll
        for (int it = 0; it < 64; ++it) {
            const int idx = tid + it * 256;
            const int r = idx >> 7, c = idx & 127;
            float v = Cs[r * 133 + c] + b1[cb * 128 + c];
            v = (v >= 0.0f) ? v : alpha * v;
            g_h[(size_t)(rb * 256 + half * 128 + r) * HID + cb * 128 + c] = v;
        }
        __syncthreads();
    }
}

// ---------------------------------------------------------------------------
// Kernel 2: LayerNorm rows of g_h -> hn quantized fp16 (float4 loads)
// ---------------------------------------------------------------------------
__global__ __launch_bounds__(128) void ln_split_kernel(
    const float* __restrict__ gamma, const float* __restrict__ beta)
{
    const int row = blockIdx.x;
    const float4* hp = (const float4*)(g_h + (size_t)row * HID);
    const int tid = threadIdx.x;

    const float4 v4 = hp[tid];
    float s  = v4.x + v4.y + v4.z + v4.w;
    float ss = v4.x * v4.x + v4.y * v4.y + v4.z * v4.z + v4.w * v4.w;
#pragma unroll
    for (int o = 16; o > 0; o >>= 1) {
        s  += __shfl_xor_sync(0xFFFFFFFFu, s,  o);
        ss += __shfl_xor_sync(0xFFFFFFFFu, ss, o);
    }
    __shared__ float sm[4], sm2[4];
    if ((tid & 31) == 0) { sm[tid >> 5] = s; sm2[tid >> 5] = ss; }
    __syncthreads();
    s  = sm[0]  + sm[1]  + sm[2]  + sm[3];
    ss = sm2[0] + sm2[1] + sm2[2] + sm2[3];

    const float mu   = s * (1.0f / HID);
    const float var  = ss * (1.0f / HID) - mu * mu;
    const float rstd = rsqrtf(var + 1e-6f);

    const float4 g4 = ((const float4*)gamma)[tid];
    const float4 b4 = ((const float4*)beta)[tid];
    __half2 o01 = __floats2half2_rn((v4.x - mu) * rstd * g4.x + b4.x,
                                    (v4.y - mu) * rstd * g4.y + b4.y);
    __half2 o23 = __floats2half2_rn((v4.z - mu) * rstd * g4.z + b4.z,
                                    (v4.w - mu) * rstd * g4.w + b4.w);
    uint2 packed;
    packed.x = *(uint32_t*)&o01;
    packed.y = *(uint32_t*)&o23;
    ((uint2*)(g_hn_h + (size_t)row * HID))[tid] = packed;
}

// ---------------------------------------------------------------------------
// Kernel 3: z = hn_q @ w2_q + b2; epilogue row-norm + zn fp16.
// tile 64x128, BK=128, 2-stage cp.async. 256 threads. grid = 128 CTAs.
// ---------------------------------------------------------------------------
#define G2_TA    (64 * 272)            // 17408
#define G2_TB    (128 * 272)           // 34816
#define G2_STAGE (G2_TA + G2_TB)       // 52224: [Aq, Bq]
#define G2_SMEM  (2 * G2_STAGE)        // 104448

__global__ __launch_bounds__(256, 1) void gemm2_mma_kernel(
    const float* __restrict__ b2, float* __restrict__ z_out)
{
    extern __shared__ char smem[];
    const uint32_t sb = smem_u32(smem);
    const int tid = threadIdx.x;
    const int wid = tid >> 5;
    const int lane = tid & 31;
    const int wm = wid & 1, wn = wid >> 1;   // 2x4 warps, warp tile 32x32
    const int rb = blockIdx.x;

    const __half* aq = g_hn_h + (size_t)(rb * 64) * HID;

    cp_t256<64, 256> (aq,      HID, sb + 0,     tid);
    cp_t256<128, 256>(g_w2t_h, HID, sb + G2_TA, tid);
    CP_COMMIT();

    const uint32_t lrow = (uint32_t)(lane & 15);
    const uint32_t lcol = (uint32_t)(lane >> 4) * 16;
    const uint32_t aoff = (uint32_t)(wm * 32) * 272 + lrow * 272 + lcol;
    const uint32_t boff = (uint32_t)(wn * 32) * 272 + lrow * 272 + lcol;

    float acc[2 * 4 * 4] = {};

    for (int kt = 0; kt < 4; ++kt) {
        if (kt < 3) {
            const int k0 = (kt + 1) * 128;
            const uint32_t st = sb + ((kt + 1) & 1) * G2_STAGE;
            cp_t256<64, 256> (aq + k0,      HID, st + 0,     tid);
            cp_t256<128, 256>(g_w2t_h + k0, HID, st + G2_TA, tid);
            CP_COMMIT();
            CP_WAIT(1);
        } else {
            CP_WAIT(0);
        }
        __syncthreads();
        const uint32_t st = sb + (kt & 1) * G2_STAGE;
        mma1<272, 8, 2, 4>(st + aoff, st + G2_TA + boff, acc);
        __syncthreads();
    }

    float* Cs = (float*)smem;
    stage_acc<2, 4>(Cs, acc, wm, wn, lane);
    __syncthreads();

    if (tid < 64) {
        const int r = tid;
        const int grow = rb * 64 + r;
        float s = 0.f;
#pragma unroll 8
        for (int c = 0; c < 128; ++c) {
            const float v = Cs[r * 133 + c] + b2[c];
            Cs[r * 133 + c] = v;
            s += v * v;
        }
        const float inv = 1.0f / fmaxf(sqrtf(s), 1e-8f);
#pragma unroll 8
        for (int c = 0; c < 128; ++c) {
            const float v = Cs[r * 133 + c];
            z_out[grow * OUT + c] = v;
            g_zn_h[grow * OUT + c] = __float2half(v * inv);
        }
    }
}

// ---------------------------------------------------------------------------
// Kernel 4: y_hat = zn_q @ zn_q^T. Pure fp16 Gram.
// 256 threads (8 warps 2x4, warp tile 64x32, NM=4/NJ=4). Each CTA: one bi
// row-band, up to 4 j-tiles; A resident, B double-buffered.
// Stage kept at 2 tiles so the consumed stage can hold the 128x133 f32 C.
// ---------------------------------------------------------------------------
#define GR_TILE  (128 * 272)           // 34816
#define GR_A     GR_TILE               // A = zn_h band
#define GR_BSTG  (2 * GR_TILE)         // stage: [Bq (tile 0), C-staging spill]
#define GR_SMEM  (GR_A + 2 * GR_BSTG)  // 174080
#define NT       (B / 128)             // 64
#define JPC      4

__global__ __launch_bounds__(256, 1) void gram_mma_kernel(float* __restrict__ yhat)
{
    int t = blockIdx.x;
    int bi = 0;
    for (; bi < NT; ++bi) {
        const int c = (NT - bi + JPC - 1) >> 2;
        if (t < c) break;
        t -= c;
    }
    const int j0 = bi + t * JPC;
    const int count = min(JPC, NT - j0);

    extern __shared__ char smem[];
    const uint32_t sb = smem_u32(smem);
    const int tid = threadIdx.x;
    const int wid = tid >> 5;
    const int lane = tid & 31;
    const int wm = wid & 1, wn = wid >> 1;   // 2x4 warps, warp tile 64x32

    cp_t256<128, 256>(g_zn_h + (size_t)(bi * 128) * OUT, OUT, sb, tid);
    cp_t256<128, 256>(g_zn_h + (size_t)(j0 * 128) * OUT, OUT,
                      sb + GR_A, tid);
    CP_COMMIT();
    if (count > 1) {
        cp_t256<128, 256>(g_zn_h + (size_t)((j0 + 1) * 128) * OUT, OUT,
                          sb + GR_A + GR_BSTG, tid);
        CP_COMMIT();
    }

    const uint32_t lrow = (uint32_t)(lane & 15);
    const uint32_t lcol = (uint32_t)(lane >> 4) * 16;
    const uint32_t aoff = (uint32_t)(wm * 64) * 272 + lrow * 272 + lcol;
    const uint32_t boff = (uint32_t)(wn * 32) * 272 + lrow * 272 + lcol;

    for (int jj = 0; jj < count; ++jj) {
        const int p = jj & 1;
        const int bj = j0 + jj;
        const uint32_t bst = sb + GR_A + p * GR_BSTG;

        if (jj + 1 < count) { CP_WAIT(1); } else { CP_WAIT(0); }
        __syncthreads();

        float acc[4 * 4 * 4] = {};
        mma1<272, 8, 4, 4>(sb + aoff, bst + boff, acc);
        __syncthreads();

        float* Cs = (float*)(smem + GR_A + p * GR_BSTG);  // consumed B stage
        stage_acc<4, 4>(Cs, acc, wm, wn, lane);
        __syncthreads();

        const long rowD = (long)bi * 128;
        const long colD = (long)bj * 128;
#pragma unroll
        for (int it = 0; it < 64; ++it) {
            const int idx = tid + it * 256;
            const int r = idx >> 7, c = idx & 127;
            yhat[(rowD + r) * (long)B + colD + c] = Cs[r * 133 + c];
        }
        if (bi != bj) {
#pragma unroll
            for (int it = 0; it < 64; ++it) {
                const int idx = tid + it * 256;
                const int r = idx >> 7, c = idx & 127;
                yhat[(colD + r) * (long)B + rowD + c] = Cs[c * 133 + r];
            }
        }
        __syncthreads();

        if (jj + 2 < count) {
            cp_t256<128, 256>(g_zn_h + ((long)(j0 + jj + 2) * 128) * OUT, OUT,
                              sb + GR_A + p * GR_BSTG, tid);
            CP_COMMIT();
        }
    }
}

#define GRAM_GRID 544   // sum over bi of ceil((NT-bi)/JPC)

// ---------------------------------------------------------------------------
extern "C" void kernel_launch(void* const* d_in, const int* in_sizes, int n_in,
                              void* d_out, int out_size)
{
    const float* x       = (const float*)d_in[0];
    const float* w1      = (const float*)d_in[1];
    const float* b1      = (const float*)d_in[2];
    const float* prelu_a = (const float*)d_in[3];
    const float* gamma   = (const float*)d_in[4];
    const float* beta    = (const float*)d_in[5];
    const float* w2      = (const float*)d_in[6];
    const float* b2      = (const float*)d_in[7];

    float* out   = (float*)d_out;
    float* z_out = out;                    // [8192, 128]
    float* yhat  = out + (size_t)B * OUT;  // [8192, 8192]

    cudaFuncSetAttribute(gemm1_mma_kernel, cudaFuncAttributeMaxDynamicSharedMemorySize, G1_SMEM);
    cudaFuncSetAttribute(gemm2_mma_kernel, cudaFuncAttributeMaxDynamicSharedMemorySize, G2_SMEM);
    cudaFuncSetAttribute(gram_mma_kernel,  cudaFuncAttributeMaxDynamicSharedMemorySize, GR_SMEM);

    split_x_kernel<<<(B * IN_DIM / 2) / 256, 256>>>(x);
    split_w1t_kernel<<<(HID * IN_DIM) / 256, 256>>>(w1);
    split_w2t_kernel<<<(OUT * HID) / 256, 256>>>(w2);

    gemm1_mma_kernel<<<dim3(HID / 128, B / 256), 256, G1_SMEM>>>(b1, prelu_a);
    ln_split_kernel<<<B, 128>>>(gamma, beta);
    gemm2_mma_kernel<<<B / 64, 256, G2_SMEM>>>(b2, z_out);
    gram_mma_kernel<<<GRAM_GRID, 256, GR_SMEM>>>(yhat);
}

// round 15
// speedup vs baseline: 1.7481x; 1.0111x over previous
#include <cuda_runtime.h>
#include <cuda_fp16.h>
#include <math.h>
#include <cstdint>

#define B      8192
#define IN_DIM 1024
#define HID    512
#define OUT    128

// scratch (device globals — no allocation allowed)
__device__ float g_h[B * HID];                               // 16 MB
__device__ __align__(256) __half g_x_h[B * IN_DIM];          // fp16 x
__device__ __align__(256) __half g_w1t_h[HID * IN_DIM];      // [n][k] fp16 w1^T
__device__ __align__(256) __half g_hn_h[B * HID];            // fp16 hn
__device__ __align__(256) __half g_w2t_h[OUT * HID];         // [n][k] fp16 w2^T
__device__ __align__(256) __half g_zn_h[B * OUT];            // fp16 zn

__device__ __forceinline__ uint32_t smem_u32(const void* p) {
    uint32_t a;
    asm("{ .reg .u64 t; cvta.to.shared.u64 t, %1; cvt.u32.u64 %0, t; }"
        : "=r"(a) : "l"(p));
    return a;
}

#define LDSM_X4(r0, r1, r2, r3, addr) \
    asm volatile("ldmatrix.sync.aligned.m8n8.x4.shared.b16 {%0,%1,%2,%3}, [%4];" \
        : "=r"(r0), "=r"(r1), "=r"(r2), "=r"(r3) : "r"(addr))

#define MMA_F16(d, a, b0, b1) \
    asm volatile("mma.sync.aligned.m16n8k16.row.col.f32.f16.f16.f32 " \
        "{%0,%1,%2,%3}, {%4,%5,%6,%7}, {%8,%9}, {%0,%1,%2,%3};" \
        : "+f"((d)[0]), "+f"((d)[1]), "+f"((d)[2]), "+f"((d)[3]) \
        : "r"((a)[0]), "r"((a)[1]), "r"((a)[2]), "r"((a)[3]), "r"(b0), "r"(b1))

#define CP16(dst, src) \
    asm volatile("cp.async.cg.shared.global [%0], [%1], 16;" \
        :: "r"(dst), "l"(src) : "memory")
#define CP_COMMIT() asm volatile("cp.async.commit_group;" ::: "memory")
#define CP_WAIT(n)  asm volatile("cp.async.wait_group %0;" :: "n"(n) : "memory")

// ---------------------------------------------------------------------------
// templated helpers
// ---------------------------------------------------------------------------
// single-product HMMA over one K-chunk: A_q * B_q
template<int RB, int NKS, int NM, int NJ>
__device__ __forceinline__ void mma1(uint32_t aQ, uint32_t bQ, float* acc)
{
#pragma unroll
    for (int ks = 0; ks < NKS; ++ks) {
        const uint32_t kb = (uint32_t)ks * 32;
        uint32_t a[NM][4];
#pragma unroll
        for (int i = 0; i < NM; ++i)
            LDSM_X4(a[i][0], a[i][1], a[i][2], a[i][3],
                    aQ + (uint32_t)i * 16 * RB + kb);
        uint32_t b[NJ][2];
#pragma unroll
        for (int p = 0; p < NJ / 2; ++p) {
            uint32_t r0, r1, r2, r3;
            LDSM_X4(r0, r1, r2, r3, bQ + (uint32_t)p * 16 * RB + kb);
            b[2 * p + 0][0] = r0; b[2 * p + 0][1] = r2;
            b[2 * p + 1][0] = r1; b[2 * p + 1][1] = r3;
        }
#pragma unroll
        for (int i = 0; i < NM; ++i)
#pragma unroll
            for (int j = 0; j < NJ; ++j)
                MMA_F16(&acc[(i * NJ + j) * 4], a[i], b[j][0], b[j][1]);
    }
}

// stage acc fragments into Cs (stride 133 floats)
template<int NM, int NJ>
__device__ __forceinline__ void stage_acc(
    float* Cs, const float* acc, int wm, int wn, int lane)
{
#pragma unroll
    for (int i = 0; i < NM; ++i) {
        const int r0 = wm * (NM * 16) + i * 16 + (lane >> 2);
#pragma unroll
        for (int j = 0; j < NJ; ++j) {
            const int c0 = wn * (NJ * 8) + j * 8 + (lane & 3) * 2;
            const float* f = &acc[(i * NJ + j) * 4];
            Cs[r0 * 133 + c0]           = f[0];
            Cs[r0 * 133 + c0 + 1]       = f[1];
            Cs[(r0 + 8) * 133 + c0]     = f[2];
            Cs[(r0 + 8) * 133 + c0 + 1] = f[3];
        }
    }
}

// cp.async ROWSx256B tile (RB=272)
template<int ROWS, int NTH>
__device__ __forceinline__ void cp_t256(
    const __half* __restrict__ g, int gstride, uint32_t dst, int tid)
{
#pragma unroll
    for (int it = 0; it < ROWS * 16 / NTH; ++it) {
        const int idx = tid + it * NTH;
        const int row = idx >> 4, c16 = idx & 15;
        CP16(dst + row * 272 + c16 * 16, g + row * gstride + c16 * 8);
    }
}

// ---------------------------------------------------------------------------
// Prologue kernels: quantize inputs to fp16 (weights transposed)
// ---------------------------------------------------------------------------
__global__ __launch_bounds__(256) void split_x_kernel(const float* __restrict__ x)
{
    const int idx = blockIdx.x * 256 + threadIdx.x;
    const float2 v = ((const float2*)x)[idx];
    g_x_h[2 * idx]     = __float2half(v.x);
    g_x_h[2 * idx + 1] = __float2half(v.y);
}

__global__ __launch_bounds__(256) void split_w1t_kernel(const float* __restrict__ w1)
{
    const int idx = blockIdx.x * 256 + threadIdx.x;
    const int n = idx >> 10, k = idx & 1023;
    g_w1t_h[idx] = __float2half(w1[k * HID + n]);
}

__global__ __launch_bounds__(256) void split_w2t_kernel(const float* __restrict__ w2)
{
    const int idx = blockIdx.x * 256 + threadIdx.x;
    const int n = idx >> 9, k = idx & 511;
    g_w2t_h[idx] = __float2half(w2[k * OUT + n]);
}

// ---------------------------------------------------------------------------
// Kernel 1: h = PReLU(x @ w1 + b1). Pure fp16 GEMM. tile 256x128, BK=128,
// 2-stage cp.async, 256 threads (8 warps 4x2, warp tile 64x64).
// ---------------------------------------------------------------------------
#define G1_TA    (256 * 272)          // 69632
#define G1_TB    (128 * 272)          // 34816
#define G1_STAGE (G1_TA + G1_TB)      // 104448: [Aq, Bq]
#define G1_SMEM  (2 * G1_STAGE)       // 208896

__global__ __launch_bounds__(256, 1) void gemm1_mma_kernel(
    const float* __restrict__ b1, const float* __restrict__ prelu_a)
{
    extern __shared__ char smem[];
    const uint32_t sb = smem_u32(smem);
    const int tid = threadIdx.x;
    const int wid = tid >> 5;
    const int lane = tid & 31;
    const int wm = wid & 3, wn = wid >> 2;   // 4x2 warps, warp tile 64x64
    const int rb = blockIdx.y, cb = blockIdx.x;

    const __half* xq = g_x_h   + (size_t)(rb * 256) * IN_DIM;
    const __half* wq = g_w1t_h + (size_t)(cb * 128) * IN_DIM;

    cp_t256<256, 256>(xq, IN_DIM, sb + 0,     tid);
    cp_t256<128, 256>(wq, IN_DIM, sb + G1_TA, tid);
    CP_COMMIT();

    const uint32_t lrow = (uint32_t)(lane & 15);
    const uint32_t lcol = (uint32_t)(lane >> 4) * 16;
    const uint32_t aoff = (uint32_t)(wm * 64) * 272 + lrow * 272 + lcol;
    const uint32_t boff = (uint32_t)(wn * 64) * 272 + lrow * 272 + lcol;

    float acc[4 * 8 * 4] = {};

    for (int kt = 0; kt < 8; ++kt) {
        if (kt < 7) {
            const int k0 = (kt + 1) * 128;
            const uint32_t st = sb + ((kt + 1) & 1) * G1_STAGE;
            cp_t256<256, 256>(xq + k0, IN_DIM, st + 0,     tid);
            cp_t256<128, 256>(wq + k0, IN_DIM, st + G1_TA, tid);
            CP_COMMIT();
            CP_WAIT(1);
        } else {
            CP_WAIT(0);
        }
        __syncthreads();
        const uint32_t st = sb + (kt & 1) * G1_STAGE;
        mma1<272, 8, 4, 8>(st + aoff, st + G1_TA + boff, acc);
        __syncthreads();
    }

    // single-pass epilogue: Cs = 256 x 133 floats = 136192 B <= 208896 B
    float* Cs = (float*)smem;
    stage_acc<4, 8>(Cs, acc, wm, wn, lane);
    __syncthreads();

    const float alpha = prelu_a[0];
#pragma unroll
    for (int it = 0; it < 128; ++it) {
        const int idx = tid + it * 256;
        const int r = idx >> 7, c = idx & 127;
        float v = Cs[r * 133 + c] + b1[cb * 128 + c];
        v = (v >= 0.0f) ? v : alpha * v;
        g_h[(size_t)(rb * 256 + r) * HID + cb * 128 + c] = v;
    }
}

// ---------------------------------------------------------------------------
// Kernel 2: LayerNorm rows of g_h -> hn quantized fp16 (float4 loads)
// ---------------------------------------------------------------------------
__global__ __launch_bounds__(128) void ln_split_kernel(
    const float* __restrict__ gamma, const float* __restrict__ beta)
{
    const int row = blockIdx.x;
    const float4* hp = (const float4*)(g_h + (size_t)row * HID);
    const int tid = threadIdx.x;

    const float4 v4 = hp[tid];
    float s  = v4.x + v4.y + v4.z + v4.w;
    float ss = v4.x * v4.x + v4.y * v4.y + v4.z * v4.z + v4.w * v4.w;
#pragma unroll
    for (int o = 16; o > 0; o >>= 1) {
        s  += __shfl_xor_sync(0xFFFFFFFFu, s,  o);
        ss += __shfl_xor_sync(0xFFFFFFFFu, ss, o);
    }
    __shared__ float sm[4], sm2[4];
    if ((tid & 31) == 0) { sm[tid >> 5] = s; sm2[tid >> 5] = ss; }
    __syncthreads();
    s  = sm[0]  + sm[1]  + sm[2]  + sm[3];
    ss = sm2[0] + sm2[1] + sm2[2] + sm2[3];

    const float mu   = s * (1.0f / HID);
    const float var  = ss * (1.0f / HID) - mu * mu;
    const float rstd = rsqrtf(var + 1e-6f);

    const float4 g4 = ((const float4*)gamma)[tid];
    const float4 b4 = ((const float4*)beta)[tid];
    __half2 o01 = __floats2half2_rn((v4.x - mu) * rstd * g4.x + b4.x,
                                    (v4.y - mu) * rstd * g4.y + b4.y);
    __half2 o23 = __floats2half2_rn((v4.z - mu) * rstd * g4.z + b4.z,
                                    (v4.w - mu) * rstd * g4.w + b4.w);
    uint2 packed;
    packed.x = *(uint32_t*)&o01;
    packed.y = *(uint32_t*)&o23;
    ((uint2*)(g_hn_h + (size_t)row * HID))[tid] = packed;
}

// ---------------------------------------------------------------------------
// Kernel 3: z = hn_q @ w2_q + b2; epilogue row-norm + zn fp16.
// tile 64x128, BK=128, 2-stage cp.async. 256 threads. grid = 128 CTAs.
// ---------------------------------------------------------------------------
#define G2_TA    (64 * 272)            // 17408
#define G2_TB    (128 * 272)           // 34816
#define G2_STAGE (G2_TA + G2_TB)       // 52224: [Aq, Bq]
#define G2_SMEM  (2 * G2_STAGE)        // 104448

__global__ __launch_bounds__(256, 1) void gemm2_mma_kernel(
    const float* __restrict__ b2, float* __restrict__ z_out)
{
    extern __shared__ char smem[];
    const uint32_t sb = smem_u32(smem);
    const int tid = threadIdx.x;
    const int wid = tid >> 5;
    const int lane = tid & 31;
    const int wm = wid & 1, wn = wid >> 1;   // 2x4 warps, warp tile 32x32
    const int rb = blockIdx.x;

    const __half* aq = g_hn_h + (size_t)(rb * 64) * HID;

    cp_t256<64, 256> (aq,      HID, sb + 0,     tid);
    cp_t256<128, 256>(g_w2t_h, HID, sb + G2_TA, tid);
    CP_COMMIT();

    const uint32_t lrow = (uint32_t)(lane & 15);
    const uint32_t lcol = (uint32_t)(lane >> 4) * 16;
    const uint32_t aoff = (uint32_t)(wm * 32) * 272 + lrow * 272 + lcol;
    const uint32_t boff = (uint32_t)(wn * 32) * 272 + lrow * 272 + lcol;

    float acc[2 * 4 * 4] = {};

    for (int kt = 0; kt < 4; ++kt) {
        if (kt < 3) {
            const int k0 = (kt + 1) * 128;
            const uint32_t st = sb + ((kt + 1) & 1) * G2_STAGE;
            cp_t256<64, 256> (aq + k0,      HID, st + 0,     tid);
            cp_t256<128, 256>(g_w2t_h + k0, HID, st + G2_TA, tid);
            CP_COMMIT();
            CP_WAIT(1);
        } else {
            CP_WAIT(0);
        }
        __syncthreads();
        const uint32_t st = sb + (kt & 1) * G2_STAGE;
        mma1<272, 8, 2, 4>(st + aoff, st + G2_TA + boff, acc);
        __syncthreads();
    }

    float* Cs = (float*)smem;
    stage_acc<2, 4>(Cs, acc, wm, wn, lane);
    __syncthreads();

    if (tid < 64) {
        const int r = tid;
        const int grow = rb * 64 + r;
        float s = 0.f;
#pragma unroll 8
        for (int c = 0; c < 128; ++c) {
            const float v = Cs[r * 133 + c] + b2[c];
            Cs[r * 133 + c] = v;
            s += v * v;
        }
        const float inv = 1.0f / fmaxf(sqrtf(s), 1e-8f);
#pragma unroll 8
        for (int c = 0; c < 128; ++c) {
            const float v = Cs[r * 133 + c];
            z_out[grow * OUT + c] = v;
            g_zn_h[grow * OUT + c] = __float2half(v * inv);
        }
    }
}

// ---------------------------------------------------------------------------
// Kernel 4: y_hat = zn_q @ zn_q^T. Pure fp16 Gram, streaming stores.
// 256 threads (8 warps 2x4, warp tile 64x32, NM=4/NJ=4). Each CTA: one bi
// row-band, up to 4 j-tiles; A resident, B double-buffered.
// ---------------------------------------------------------------------------
#define GR_TILE  (128 * 272)           // 34816
#define GR_A     GR_TILE               // A = zn_h band
#define GR_BSTG  (2 * GR_TILE)         // stage: [Bq (tile 0), C-staging spill]
#define GR_SMEM  (GR_A + 2 * GR_BSTG)  // 174080
#define NT       (B / 128)             // 64
#define JPC      4

__global__ __launch_bounds__(256, 1) void gram_mma_kernel(float* __restrict__ yhat)
{
    int t = blockIdx.x;
    int bi = 0;
    for (; bi < NT; ++bi) {
        const int c = (NT - bi + JPC - 1) >> 2;
        if (t < c) break;
        t -= c;
    }
    const int j0 = bi + t * JPC;
    const int count = min(JPC, NT - j0);

    extern __shared__ char smem[];
    const uint32_t sb = smem_u32(smem);
    const int tid = threadIdx.x;
    const int wid = tid >> 5;
    const int lane = tid & 31;
    const int wm = wid & 1, wn = wid >> 1;   // 2x4 warps, warp tile 64x32

    cp_t256<128, 256>(g_zn_h + (size_t)(bi * 128) * OUT, OUT, sb, tid);
    cp_t256<128, 256>(g_zn_h + (size_t)(j0 * 128) * OUT, OUT,
                      sb + GR_A, tid);
    CP_COMMIT();
    if (count > 1) {
        cp_t256<128, 256>(g_zn_h + (size_t)((j0 + 1) * 128) * OUT, OUT,
                          sb + GR_A + GR_BSTG, tid);
        CP_COMMIT();
    }

    const uint32_t lrow = (uint32_t)(lane & 15);
    const uint32_t lcol = (uint32_t)(lane >> 4) * 16;
    const uint32_t aoff = (uint32_t)(wm * 64) * 272 + lrow * 272 + lcol;
    const uint32_t boff = (uint32_t)(wn * 32) * 272 + lrow * 272 + lcol;

    for (int jj = 0; jj < count; ++jj) {
        const int p = jj & 1;
        const int bj = j0 + jj;
        const uint32_t bst = sb + GR_A + p * GR_BSTG;

        if (jj + 1 < count) { CP_WAIT(1); } else { CP_WAIT(0); }
        __syncthreads();

        float acc[4 * 4 * 4] = {};
        mma1<272, 8, 4, 4>(sb + aoff, bst + boff, acc);
        __syncthreads();

        float* Cs = (float*)(smem + GR_A + p * GR_BSTG);  // consumed B stage
        stage_acc<4, 4>(Cs, acc, wm, wn, lane);
        __syncthreads();

        const long rowD = (long)bi * 128;
        const long colD = (long)bj * 128;
#pragma unroll
        for (int it = 0; it < 64; ++it) {
            const int idx = tid + it * 256;
            const int r = idx >> 7, c = idx & 127;
            __stcs(&yhat[(rowD + r) * (long)B + colD + c], Cs[r * 133 + c]);
        }
        if (bi != bj) {
#pragma unroll
            for (int it = 0; it < 64; ++it) {
                const int idx = tid + it * 256;
                const int r = idx >> 7, c = idx & 127;
                __stcs(&yhat[(colD + r) * (long)B + rowD + c], Cs[c * 133 + r]);
            }
        }
        __syncthreads();

        if (jj + 2 < count) {
            cp_t256<128, 256>(g_zn_h + ((long)(j0 + jj + 2) * 128) * OUT, OUT,
                              sb + GR_A + p * GR_BSTG, tid);
            CP_COMMIT();
        }
    }
}

#define GRAM_GRID 544   // sum over bi of ceil((NT-bi)/JPC)

// ---------------------------------------------------------------------------
extern "C" void kernel_launch(void* const* d_in, const int* in_sizes, int n_in,
                              void* d_out, int out_size)
{
    const float* x       = (const float*)d_in[0];
    const float* w1      = (const float*)d_in[1];
    const float* b1      = (const float*)d_in[2];
    const float* prelu_a = (const float*)d_in[3];
    const float* gamma   = (const float*)d_in[4];
    const float* beta    = (const float*)d_in[5];
    const float* w2      = (const float*)d_in[6];
    const float* b2      = (const float*)d_in[7];

    float* out   = (float*)d_out;
    float* z_out = out;                    // [8192, 128]
    float* yhat  = out + (size_t)B * OUT;  // [8192, 8192]

    cudaFuncSetAttribute(gemm1_mma_kernel, cudaFuncAttributeMaxDynamicSharedMemorySize, G1_SMEM);
    cudaFuncSetAttribute(gemm2_mma_kernel, cudaFuncAttributeMaxDynamicSharedMemorySize, G2_SMEM);
    cudaFuncSetAttribute(gram_mma_kernel,  cudaFuncAttributeMaxDynamicSharedMemorySize, GR_SMEM);

    split_x_kernel<<<(B * IN_DIM / 2) / 256, 256>>>(x);
    split_w1t_kernel<<<(HID * IN_DIM) / 256, 256>>>(w1);
    split_w2t_kernel<<<(OUT * HID) / 256, 256>>>(w2);

    gemm1_mma_kernel<<<dim3(HID / 128, B / 256), 256, G1_SMEM>>>(b1, prelu_a);
    ln_split_kernel<<<B, 128>>>(gamma, beta);
    gemm2_mma_kernel<<<B / 64, 256, G2_SMEM>>>(b2, z_out);
    gram_mma_kernel<<<GRAM_GRID, 256, GR_SMEM>>>(yhat);
}